// round 3
// baseline (speedup 1.0000x reference)
#include <cuda_runtime.h>
#include <math.h>

#define Bb 2
#define Tt 512
#define Cc 768
#define Hh 12
#define HS 64
#define BHn (Bb*Hh)

// scratch (allocation-free rule: __device__ globals)
__device__ float g_q[BHn*Tt*HS];
__device__ float g_k[BHn*Tt*HS];
__device__ float g_v[BHn*Tt*HS];
__device__ float g_y[Bb*Tt*Cc];

// lexicographic pairs (a<b) over 8 slots, matching itertools.combinations order
__constant__ int cPA[28] = {0,0,0,0,0,0,0,1,1,1,1,1,1,2,2,2,2,2,3,3,3,3,4,4,4,5,5,6};
__constant__ int cPB[28] = {1,2,3,4,5,6,7,2,3,4,5,6,7,3,4,5,6,7,4,5,6,7,5,6,7,6,7,7};

// ---------------------------------------------------------------------------
// GEMM: C[m,n] = sum_k A[m,k]*B[n,k] + bias[n]   (NT, fp32)
// 64x64 tile, 256 threads, 4x4 micro-tile, BK=16
// ---------------------------------------------------------------------------
#define BM 64
#define BN 64
#define BK 16

__global__ void __launch_bounds__(256) gemm_qkv_kernel(
    const float* __restrict__ A,     // x [1024,768]
    const float* __restrict__ Bm,    // W_attn [2304,768]
    const float* __restrict__ bias)  // b_attn [2304]
{
    const int K = Cc;
    __shared__ __align__(16) float As[BK][BM+4];
    __shared__ __align__(16) float Bs[BK][BN+4];
    int tid = threadIdx.x;
    int tx = tid & 15, ty = tid >> 4;
    int m0 = blockIdx.y * BM, n0 = blockIdx.x * BN;
    int lr = tid >> 2;
    int lk = (tid & 3) << 2;
    float acc[4][4] = {};
    for (int k0 = 0; k0 < K; k0 += BK) {
        float4 av = *(const float4*)(A  + (size_t)(m0+lr)*K + k0 + lk);
        float4 bv = *(const float4*)(Bm + (size_t)(n0+lr)*K + k0 + lk);
        As[lk+0][lr]=av.x; As[lk+1][lr]=av.y; As[lk+2][lr]=av.z; As[lk+3][lr]=av.w;
        Bs[lk+0][lr]=bv.x; Bs[lk+1][lr]=bv.y; Bs[lk+2][lr]=bv.z; Bs[lk+3][lr]=bv.w;
        __syncthreads();
#pragma unroll
        for (int kk = 0; kk < BK; kk++) {
            float4 a = *(const float4*)&As[kk][ty<<2];
            float4 b = *(const float4*)&Bs[kk][tx<<2];
            acc[0][0]+=a.x*b.x; acc[0][1]+=a.x*b.y; acc[0][2]+=a.x*b.z; acc[0][3]+=a.x*b.w;
            acc[1][0]+=a.y*b.x; acc[1][1]+=a.y*b.y; acc[1][2]+=a.y*b.z; acc[1][3]+=a.y*b.w;
            acc[2][0]+=a.z*b.x; acc[2][1]+=a.z*b.y; acc[2][2]+=a.z*b.z; acc[2][3]+=a.z*b.w;
            acc[3][0]+=a.w*b.x; acc[3][1]+=a.w*b.y; acc[3][2]+=a.w*b.z; acc[3][3]+=a.w*b.w;
        }
        __syncthreads();
    }
    // scatter epilogue: n -> (q|k|v, head, d), m -> (b, t)
#pragma unroll
    for (int im = 0; im < 4; im++) {
#pragma unroll
        for (int in = 0; in < 4; in++) {
            int m = m0 + (ty<<2) + im;
            int n = n0 + (tx<<2) + in;
            float val = acc[im][in] + bias[n];
            int part = n / Cc;
            int c = n - part*Cc;
            int h = c >> 6;
            int d = c & 63;
            int b = m >> 9;
            int t = m & 511;
            float* dst = (part==0) ? g_q : (part==1) ? g_k : g_v;
            dst[(((size_t)(b*Hh + h))*Tt + t)*HS + d] = val;
        }
    }
}

__global__ void __launch_bounds__(256) gemm_proj_kernel(
    const float* __restrict__ Bm,    // W_proj [768,768]
    const float* __restrict__ bias,  // b_proj [768]
    float* __restrict__ out)         // [1024,768]
{
    const int K = Cc;
    const float* A = g_y;
    __shared__ __align__(16) float As[BK][BM+4];
    __shared__ __align__(16) float Bs[BK][BN+4];
    int tid = threadIdx.x;
    int tx = tid & 15, ty = tid >> 4;
    int m0 = blockIdx.y * BM, n0 = blockIdx.x * BN;
    int lr = tid >> 2;
    int lk = (tid & 3) << 2;
    float acc[4][4] = {};
    for (int k0 = 0; k0 < K; k0 += BK) {
        float4 av = *(const float4*)(A  + (size_t)(m0+lr)*K + k0 + lk);
        float4 bv = *(const float4*)(Bm + (size_t)(n0+lr)*K + k0 + lk);
        As[lk+0][lr]=av.x; As[lk+1][lr]=av.y; As[lk+2][lr]=av.z; As[lk+3][lr]=av.w;
        Bs[lk+0][lr]=bv.x; Bs[lk+1][lr]=bv.y; Bs[lk+2][lr]=bv.z; Bs[lk+3][lr]=bv.w;
        __syncthreads();
#pragma unroll
        for (int kk = 0; kk < BK; kk++) {
            float4 a = *(const float4*)&As[kk][ty<<2];
            float4 b = *(const float4*)&Bs[kk][tx<<2];
            acc[0][0]+=a.x*b.x; acc[0][1]+=a.x*b.y; acc[0][2]+=a.x*b.z; acc[0][3]+=a.x*b.w;
            acc[1][0]+=a.y*b.x; acc[1][1]+=a.y*b.y; acc[1][2]+=a.y*b.z; acc[1][3]+=a.y*b.w;
            acc[2][0]+=a.z*b.x; acc[2][1]+=a.z*b.y; acc[2][2]+=a.z*b.z; acc[2][3]+=a.z*b.w;
            acc[3][0]+=a.w*b.x; acc[3][1]+=a.w*b.y; acc[3][2]+=a.w*b.z; acc[3][3]+=a.w*b.w;
        }
        __syncthreads();
    }
#pragma unroll
    for (int im = 0; im < 4; im++) {
#pragma unroll
        for (int in = 0; in < 4; in++) {
            int m = m0 + (ty<<2) + im;
            int n = n0 + (tx<<2) + in;
            out[(size_t)m*Cc + n] = acc[im][in] + bias[n];
        }
    }
}

// ---------------------------------------------------------------------------
// DPP kernel: one block per (token i, head)
// ---------------------------------------------------------------------------
__global__ void __launch_bounds__(256) dpp_kernel() {
    const int i    = blockIdx.x;
    const int head = blockIdx.y;
    const int tid  = threadIdx.x;
    const float* qh = g_q + (size_t)head*Tt*HS;
    const float* kh = g_k + (size_t)head*Tt*HS;
    const float* vh = g_v + (size_t)head*Tt*HS;

    __shared__ __align__(16) float sq[HS];
    __shared__ float sims[Tt];
    __shared__ float rv[256];
    __shared__ int   ri[256];
    __shared__ int   sTop[8];
    __shared__ int   sRows[9];
    __shared__ float skr[9][HS+1];
    __shared__ float svr[9][HS+1];
    __shared__ float sG[9][9];
    __shared__ float sdv[9];
    __shared__ float sScore[36];
    __shared__ float sWw[36][3];
    __shared__ float sCoeff[9];

    if (tid < HS) sq[tid] = qh[(size_t)i*HS + tid];
    __syncthreads();

    // --- sims over causal range [0, i] ---
    const float4* q4 = (const float4*)sq;
    for (int j = tid; j <= i; j += 256) {
        const float4* kr = (const float4*)(kh + (size_t)j*HS);
        float s = 0.f;
#pragma unroll
        for (int t = 0; t < 16; t++) {
            float4 kv = kr[t]; float4 qv = q4[t];
            s += kv.x*qv.x + kv.y*qv.y + kv.z*qv.z + kv.w*qv.w;
        }
        sims[j] = s;
    }
    __syncthreads();

    const int ncand = (i+1 < 8) ? (i+1) : 8;

    // --- top-8, tie-break lowest index (jax.lax.top_k semantics) ---
    for (int r = 0; r < 8; r++) {
        float bv = -INFINITY; int bi = 0x7fffffff;
        for (int j = tid; j <= i; j += 256) {
            float v = sims[j];
            if (v > bv || (v == bv && j < bi)) { bv = v; bi = j; }
        }
        rv[tid] = bv; ri[tid] = bi;
        __syncthreads();
        for (int s = 128; s > 0; s >>= 1) {
            if (tid < s) {
                float ov = rv[tid+s]; int oi = ri[tid+s];
                if (ov > rv[tid] || (ov == rv[tid] && oi < ri[tid])) { rv[tid]=ov; ri[tid]=oi; }
            }
            __syncthreads();
        }
        if (tid == 0) {
            int sel = ri[0];
            if (sel < 0 || sel > i) sel = 0;   // safety; only hits padding slots
            sTop[r] = sel;
            sims[sel] = -INFINITY;
        }
        __syncthreads();
    }

    if (tid == 0) {
        sRows[0] = i;
#pragma unroll
        for (int r = 0; r < 8; r++) sRows[r+1] = sTop[r];
    }
    __syncthreads();

    // --- stage the (up to) 9 distinct k/v rows ---
    for (int e = tid; e < 9*HS; e += 256) {
        int r = e >> 6, d = e & 63;
        int row = sRows[r];
        skr[r][d] = kh[(size_t)row*HS + d];
        svr[r][d] = vh[(size_t)row*HS + d];
    }
    __syncthreads();

    // --- Gram matrix (9x9) and q-dots (scaled by 1/sqrt(64)) ---
    if (tid < 81) {
        int r = tid / 9, c = tid % 9;
        float s = 0.f;
        for (int d = 0; d < HS; d++) s += skr[r][d]*skr[c][d];
        sG[r][c] = s;
    } else if (tid >= 96 && tid < 105) {
        int r = tid - 96;
        float s = 0.f;
        for (int d = 0; d < HS; d++) s += skr[r][d]*sq[d];
        sdv[r] = s * 0.125f;
    }
    __syncthreads();

    // --- 36 combos: score + member softmax weights ---
    if (tid < 36) {
        int a, b, sz;
        if (tid < 8) { sz = 2; a = tid; b = -1; }
        else         { sz = 3; a = cPA[tid-8]; b = cPB[tid-8]; }
        bool valid = (a < ncand) && (sTop[a] != i);
        if (b >= 0) valid = valid && (b < ncand) && (sTop[b] != i);
        float score = -INFINITY, w0 = 0.f, w1 = 0.f, w2 = 0.f;
        if (valid) {
            int ra = a + 1;
            if (sz == 2) {
                float det = sG[0][0]*sG[ra][ra] - sG[0][ra]*sG[0][ra];
                score = logf(det + 1e-6f) * 0.5f;
                float d0 = sdv[0], d1 = sdv[ra];
                float m = fmaxf(d0, d1);
                float e0 = expf(d0-m), e1 = expf(d1-m);
                float inv = 1.f/(e0+e1);
                w0 = e0*inv; w1 = e1*inv;
            } else {
                int rb = b + 1;
                float g00=sG[0][0],  g01=sG[0][ra],  g02=sG[0][rb];
                float g11=sG[ra][ra], g12=sG[ra][rb], g22=sG[rb][rb];
                float det = g00*(g11*g22 - g12*g12)
                          - g01*(g01*g22 - g12*g02)
                          + g02*(g01*g12 - g11*g02);
                score = logf(det + 1e-6f) * (1.f/3.f);
                float d0=sdv[0], d1=sdv[ra], d2=sdv[rb];
                float m = fmaxf(d0, fmaxf(d1, d2));
                float e0=expf(d0-m), e1=expf(d1-m), e2=expf(d2-m);
                float inv = 1.f/(e0+e1+e2);
                w0=e0*inv; w1=e1*inv; w2=e2*inv;
            }
        }
        sScore[tid] = score;
        sWw[tid][0] = w0; sWw[tid][1] = w1; sWw[tid][2] = w2;
    }
    __syncthreads();

    // --- softmax over combo scores, accumulate per-row coefficients ---
    if (tid == 0) {
        float mx = -INFINITY;
        for (int c = 0; c < 36; c++) mx = fmaxf(mx, sScore[c]);
        for (int r = 0; r < 9; r++) sCoeff[r] = 0.f;
        if (mx == -INFINITY) {
            sCoeff[0] = 1.f;          // no valid subset -> y = v[i]
        } else {
            float sum = 0.f;
            for (int c = 0; c < 36; c++)
                if (sScore[c] != -INFINITY) sum += expf(sScore[c]-mx);
            float invs = 1.f/sum;
            for (int c = 0; c < 36; c++) {
                if (sScore[c] == -INFINITY) continue;
                float p = expf(sScore[c]-mx)*invs;
                sCoeff[0] += p * sWw[c][0];
                int a = (c < 8) ? c : cPA[c-8];
                sCoeff[a+1] += p * sWw[c][1];
                if (c >= 8) { int b = cPB[c-8]; sCoeff[b+1] += p * sWw[c][2]; }
            }
        }
    }
    __syncthreads();

    // --- y = sum_r coeff[r]*v[r], scatter to [B,T,C] layout ---
    if (tid < HS) {
        float y = 0.f;
#pragma unroll
        for (int r = 0; r < 9; r++) y += sCoeff[r]*svr[r][tid];
        int bb = head / Hh, h = head - bb*Hh;
        g_y[((size_t)(bb*Tt + i))*Cc + h*HS + tid] = y;
    }
}

// ---------------------------------------------------------------------------
extern "C" void kernel_launch(void* const* d_in, const int* in_sizes, int n_in,
                              void* d_out, int out_size) {
    const float* x      = (const float*)d_in[0];
    const float* W_attn = (const float*)d_in[1];
    const float* b_attn = (const float*)d_in[2];
    const float* W_proj = (const float*)d_in[3];
    const float* b_proj = (const float*)d_in[4];
    float* out = (float*)d_out;

    dim3 blk(256);
    dim3 g1(3*Cc/BN, Bb*Tt/BM);   // 36 x 16
    gemm_qkv_kernel<<<g1, blk>>>(x, W_attn, b_attn);

    dim3 g2(Tt, BHn);             // 512 x 24
    dpp_kernel<<<g2, blk>>>();

    dim3 g3(Cc/BN, Bb*Tt/BM);     // 12 x 16
    gemm_proj_kernel<<<g3, blk>>>(W_proj, b_proj, out);
}

// round 4
// speedup vs baseline: 4.3083x; 4.3083x over previous
#include <cuda_runtime.h>
#include <math.h>

#define Bb 2
#define Tt 512
#define Cc 768
#define Hh 12
#define HS 64
#define BHn (Bb*Hh)

// scratch (allocation-free rule: __device__ globals)
__device__ float g_q[BHn*Tt*HS];
__device__ float g_k[BHn*Tt*HS];
__device__ float g_v[BHn*Tt*HS];
__device__ float g_y[Bb*Tt*Cc];
__device__ float g_s[(size_t)BHn*Tt*Tt];   // causal sim matrix per head (lower triangle valid)

// lexicographic pairs (a<b) over 8 slots, matching itertools.combinations order
__constant__ int cPA[28] = {0,0,0,0,0,0,0,1,1,1,1,1,1,2,2,2,2,2,3,3,3,3,4,4,4,5,5,6};
__constant__ int cPB[28] = {1,2,3,4,5,6,7,2,3,4,5,6,7,3,4,5,6,7,4,5,6,7,5,6,7,6,7,7};

// 54 dot-tasks: 45 gram pairs (r<=c) + 9 q-dots (c==9 means q)
__constant__ int cTR[54] = {0,0,0,0,0,0,0,0,0, 1,1,1,1,1,1,1,1, 2,2,2,2,2,2,2,
                            3,3,3,3,3,3, 4,4,4,4,4, 5,5,5,5, 6,6,6, 7,7, 8,
                            0,1,2,3,4,5,6,7,8};
__constant__ int cTC[54] = {0,1,2,3,4,5,6,7,8, 1,2,3,4,5,6,7,8, 2,3,4,5,6,7,8,
                            3,4,5,6,7,8, 4,5,6,7,8, 5,6,7,8, 6,7,8, 7,8, 8,
                            9,9,9,9,9,9,9,9,9};

// ---------------------------------------------------------------------------
// GEMM: C[m,n] = sum_k A[m,k]*B[n,k] + bias[n]   (NT, fp32)
// ---------------------------------------------------------------------------
#define BM 64
#define BN 64
#define BK 16

__global__ void __launch_bounds__(256) gemm_qkv_kernel(
    const float* __restrict__ A,     // x [1024,768]
    const float* __restrict__ Bm,    // W_attn [2304,768]
    const float* __restrict__ bias)  // b_attn [2304]
{
    const int K = Cc;
    __shared__ __align__(16) float As[BK][BM+4];
    __shared__ __align__(16) float Bs[BK][BN+4];
    int tid = threadIdx.x;
    int tx = tid & 15, ty = tid >> 4;
    int m0 = blockIdx.y * BM, n0 = blockIdx.x * BN;
    int lr = tid >> 2;
    int lk = (tid & 3) << 2;
    float acc[4][4] = {};
    for (int k0 = 0; k0 < K; k0 += BK) {
        float4 av = *(const float4*)(A  + (size_t)(m0+lr)*K + k0 + lk);
        float4 bv = *(const float4*)(Bm + (size_t)(n0+lr)*K + k0 + lk);
        As[lk+0][lr]=av.x; As[lk+1][lr]=av.y; As[lk+2][lr]=av.z; As[lk+3][lr]=av.w;
        Bs[lk+0][lr]=bv.x; Bs[lk+1][lr]=bv.y; Bs[lk+2][lr]=bv.z; Bs[lk+3][lr]=bv.w;
        __syncthreads();
#pragma unroll
        for (int kk = 0; kk < BK; kk++) {
            float4 a = *(const float4*)&As[kk][ty<<2];
            float4 b = *(const float4*)&Bs[kk][tx<<2];
            acc[0][0]+=a.x*b.x; acc[0][1]+=a.x*b.y; acc[0][2]+=a.x*b.z; acc[0][3]+=a.x*b.w;
            acc[1][0]+=a.y*b.x; acc[1][1]+=a.y*b.y; acc[1][2]+=a.y*b.z; acc[1][3]+=a.y*b.w;
            acc[2][0]+=a.z*b.x; acc[2][1]+=a.z*b.y; acc[2][2]+=a.z*b.z; acc[2][3]+=a.z*b.w;
            acc[3][0]+=a.w*b.x; acc[3][1]+=a.w*b.y; acc[3][2]+=a.w*b.z; acc[3][3]+=a.w*b.w;
        }
        __syncthreads();
    }
#pragma unroll
    for (int im = 0; im < 4; im++) {
#pragma unroll
        for (int in = 0; in < 4; in++) {
            int m = m0 + (ty<<2) + im;
            int n = n0 + (tx<<2) + in;
            float val = acc[im][in] + bias[n];
            int part = n / Cc;
            int c = n - part*Cc;
            int h = c >> 6;
            int d = c & 63;
            int b = m >> 9;
            int t = m & 511;
            float* dst = (part==0) ? g_q : (part==1) ? g_k : g_v;
            dst[(((size_t)(b*Hh + h))*Tt + t)*HS + d] = val;
        }
    }
}

__global__ void __launch_bounds__(256) gemm_proj_kernel(
    const float* __restrict__ Bm,    // W_proj [768,768]
    const float* __restrict__ bias,  // b_proj [768]
    float* __restrict__ out)         // [1024,768]
{
    const int K = Cc;
    const float* A = g_y;
    __shared__ __align__(16) float As[BK][BM+4];
    __shared__ __align__(16) float Bs[BK][BN+4];
    int tid = threadIdx.x;
    int tx = tid & 15, ty = tid >> 4;
    int m0 = blockIdx.y * BM, n0 = blockIdx.x * BN;
    int lr = tid >> 2;
    int lk = (tid & 3) << 2;
    float acc[4][4] = {};
    for (int k0 = 0; k0 < K; k0 += BK) {
        float4 av = *(const float4*)(A  + (size_t)(m0+lr)*K + k0 + lk);
        float4 bv = *(const float4*)(Bm + (size_t)(n0+lr)*K + k0 + lk);
        As[lk+0][lr]=av.x; As[lk+1][lr]=av.y; As[lk+2][lr]=av.z; As[lk+3][lr]=av.w;
        Bs[lk+0][lr]=bv.x; Bs[lk+1][lr]=bv.y; Bs[lk+2][lr]=bv.z; Bs[lk+3][lr]=bv.w;
        __syncthreads();
#pragma unroll
        for (int kk = 0; kk < BK; kk++) {
            float4 a = *(const float4*)&As[kk][ty<<2];
            float4 b = *(const float4*)&Bs[kk][tx<<2];
            acc[0][0]+=a.x*b.x; acc[0][1]+=a.x*b.y; acc[0][2]+=a.x*b.z; acc[0][3]+=a.x*b.w;
            acc[1][0]+=a.y*b.x; acc[1][1]+=a.y*b.y; acc[1][2]+=a.y*b.z; acc[1][3]+=a.y*b.w;
            acc[2][0]+=a.z*b.x; acc[2][1]+=a.z*b.y; acc[2][2]+=a.z*b.z; acc[2][3]+=a.z*b.w;
            acc[3][0]+=a.w*b.x; acc[3][1]+=a.w*b.y; acc[3][2]+=a.w*b.z; acc[3][3]+=a.w*b.w;
        }
        __syncthreads();
    }
#pragma unroll
    for (int im = 0; im < 4; im++) {
#pragma unroll
        for (int in = 0; in < 4; in++) {
            int m = m0 + (ty<<2) + im;
            int n = n0 + (tx<<2) + in;
            out[(size_t)m*Cc + n] = acc[im][in] + bias[n];
        }
    }
}

// ---------------------------------------------------------------------------
// sims kernel: S[h][i][j] = q_i . k_j  for lower-triangular 64x64 blocks
// ---------------------------------------------------------------------------
__global__ void __launch_bounds__(256) sims_kernel() {
    if (blockIdx.x > blockIdx.y) return;          // entirely j > i : never read
    const int head = blockIdx.z;
    const int m0 = blockIdx.y * 64;               // i range
    const int n0 = blockIdx.x * 64;               // j range
    const float* Qh = g_q + (size_t)head*Tt*HS;
    const float* Kh = g_k + (size_t)head*Tt*HS;
    float* Sh = g_s + (size_t)head*Tt*Tt;

    __shared__ __align__(16) float As[BK][BM+4];
    __shared__ __align__(16) float Bs[BK][BN+4];
    int tid = threadIdx.x;
    int tx = tid & 15, ty = tid >> 4;
    int lr = tid >> 2;
    int lk = (tid & 3) << 2;
    float acc[4][4] = {};
    for (int k0 = 0; k0 < HS; k0 += BK) {
        float4 av = *(const float4*)(Qh + (size_t)(m0+lr)*HS + k0 + lk);
        float4 bv = *(const float4*)(Kh + (size_t)(n0+lr)*HS + k0 + lk);
        As[lk+0][lr]=av.x; As[lk+1][lr]=av.y; As[lk+2][lr]=av.z; As[lk+3][lr]=av.w;
        Bs[lk+0][lr]=bv.x; Bs[lk+1][lr]=bv.y; Bs[lk+2][lr]=bv.z; Bs[lk+3][lr]=bv.w;
        __syncthreads();
#pragma unroll
        for (int kk = 0; kk < BK; kk++) {
            float4 a = *(const float4*)&As[kk][ty<<2];
            float4 b = *(const float4*)&Bs[kk][tx<<2];
            acc[0][0]+=a.x*b.x; acc[0][1]+=a.x*b.y; acc[0][2]+=a.x*b.z; acc[0][3]+=a.x*b.w;
            acc[1][0]+=a.y*b.x; acc[1][1]+=a.y*b.y; acc[1][2]+=a.y*b.z; acc[1][3]+=a.y*b.w;
            acc[2][0]+=a.z*b.x; acc[2][1]+=a.z*b.y; acc[2][2]+=a.z*b.z; acc[2][3]+=a.z*b.w;
            acc[3][0]+=a.w*b.x; acc[3][1]+=a.w*b.y; acc[3][2]+=a.w*b.z; acc[3][3]+=a.w*b.w;
        }
        __syncthreads();
    }
#pragma unroll
    for (int im = 0; im < 4; im++) {
#pragma unroll
        for (int in = 0; in < 4; in++) {
            int m = m0 + (ty<<2) + im;
            int n = n0 + (tx<<2) + in;
            Sh[(size_t)m*Tt + n] = acc[im][in];   // reader masks j>i
        }
    }
}

// ---------------------------------------------------------------------------
// DPP score kernel: WARP per (token, head). 8 warps/block, no block barriers.
// ---------------------------------------------------------------------------
#define NW 8
#define FULLMASK 0xffffffffu

__global__ void __launch_bounds__(256) dpp_score_kernel() {
    const int lane = threadIdx.x & 31;
    const int w    = threadIdx.x >> 5;
    const int i    = blockIdx.x * NW + w;
    const int head = blockIdx.y;

    const float* qh = g_q + (size_t)head*Tt*HS;
    const float* kh = g_k + (size_t)head*Tt*HS;
    const float* vh = g_v + (size_t)head*Tt*HS;
    const float* srow = g_s + ((size_t)head*Tt + i)*Tt;

    __shared__ float skr[NW][10][HS+1];   // 9 k rows + q row (index 9)
    __shared__ float svr[NW][9][HS+1];
    __shared__ float sG[NW][9][9];
    __shared__ float sdv[NW][9];
    __shared__ int   sRows[NW][9];
    __shared__ float sCoeff[NW][9];

    // --- sims row into registers (masked causal) ---
    float sv[16];
#pragma unroll
    for (int c = 0; c < 16; c++) {
        int j = lane + (c << 5);
        sv[c] = (j <= i) ? srow[j] : -INFINITY;
    }

    const int ncand = (i + 1 < 8) ? (i + 1) : 8;

    // --- top-8 via warp shfl argmax, min-index tiebreak ---
    int top[8];
#pragma unroll
    for (int r = 0; r < 8; r++) {
        float bv = -INFINITY; int bi = 0x7fffffff;
#pragma unroll
        for (int c = 0; c < 16; c++) {
            int j = lane + (c << 5);
            float v = sv[c];
            if (v > bv || (v == bv && j < bi)) { bv = v; bi = j; }
        }
#pragma unroll
        for (int off = 16; off > 0; off >>= 1) {
            float ov = __shfl_xor_sync(FULLMASK, bv, off);
            int   oi = __shfl_xor_sync(FULLMASK, bi, off);
            if (ov > bv || (ov == bv && oi < bi)) { bv = ov; bi = oi; }
        }
        int sel = bi;
        if (sel < 0 || sel > i) sel = 0;
        top[r] = sel;
        if ((sel & 31) == lane) sv[sel >> 5] = -INFINITY;
    }

    if (lane == 0) {
        sRows[w][0] = i;
        sRows[w][1] = top[0]; sRows[w][2] = top[1]; sRows[w][3] = top[2];
        sRows[w][4] = top[3]; sRows[w][5] = top[4]; sRows[w][6] = top[5];
        sRows[w][7] = top[6]; sRows[w][8] = top[7];
    }
    __syncwarp();

    // --- stage 9 k rows + q + 9 v rows ---
    for (int e = lane; e < 9*HS; e += 32) {
        int r = e >> 6, d = e & 63;
        int row = sRows[w][r];
        skr[w][r][d] = kh[(size_t)row*HS + d];
        svr[w][r][d] = vh[(size_t)row*HS + d];
    }
    for (int d = lane; d < HS; d += 32)
        skr[w][9][d] = qh[(size_t)i*HS + d];
    __syncwarp();

    // --- 54 dot tasks: 45 gram pairs + 9 q-dots ---
    {
        int t0 = lane, t1 = lane + 32;
        int r0 = cTR[t0], c0 = cTC[t0];
        int r1 = (t1 < 54) ? cTR[t1] : 0;
        int c1 = (t1 < 54) ? cTC[t1] : 0;
        float a0 = 0.f, a1 = 0.f;
#pragma unroll
        for (int d = 0; d < HS; d++) {
            a0 += skr[w][r0][d] * skr[w][c0][d];
            a1 += skr[w][r1][d] * skr[w][c1][d];
        }
        if (c0 == 9) sdv[w][r0] = a0 * 0.125f;
        else { sG[w][r0][c0] = a0; sG[w][c0][r0] = a0; }
        if (t1 < 54) {
            if (c1 == 9) sdv[w][r1] = a1 * 0.125f;
            else { sG[w][r1][c1] = a1; sG[w][c1][r1] = a1; }
        }
    }
    __syncwarp();

    // --- per-lane combos (lane and lane+32) ---
    float sc0 = -INFINITY, sc1 = -INFINITY;
    float w00=0,w01=0,w02=0, w10=0,w11=0,w12=0;
    int a0i=-1, b0i=-1, a1i=-1, b1i=-1;
#pragma unroll
    for (int half = 0; half < 2; half++) {
        int cid = lane + (half << 5);
        if (cid >= 36) break;
        int a, b, sz;
        if (cid < 8) { sz = 2; a = cid; b = -1; }
        else         { sz = 3; a = cPA[cid-8]; b = cPB[cid-8]; }
        bool valid = (a < ncand) && (sRows[w][a+1] != i);
        if (b >= 0) valid = valid && (b < ncand) && (sRows[w][b+1] != i);
        float score = -INFINITY, x0 = 0.f, x1 = 0.f, x2 = 0.f;
        if (valid) {
            int ra = a + 1;
            if (sz == 2) {
                float det = sG[w][0][0]*sG[w][ra][ra] - sG[w][0][ra]*sG[w][0][ra];
                score = logf(det + 1e-6f) * 0.5f;
                float d0 = sdv[w][0], d1 = sdv[w][ra];
                float m = fmaxf(d0, d1);
                float e0 = expf(d0-m), e1 = expf(d1-m);
                float inv = 1.f/(e0+e1);
                x0 = e0*inv; x1 = e1*inv;
            } else {
                int rb = b + 1;
                float g00=sG[w][0][0],  g01=sG[w][0][ra],  g02=sG[w][0][rb];
                float g11=sG[w][ra][ra], g12=sG[w][ra][rb], g22=sG[w][rb][rb];
                float det = g00*(g11*g22 - g12*g12)
                          - g01*(g01*g22 - g12*g02)
                          + g02*(g01*g12 - g11*g02);
                score = logf(det + 1e-6f) * (1.f/3.f);
                float d0=sdv[w][0], d1=sdv[w][ra], d2=sdv[w][rb];
                float m = fmaxf(d0, fmaxf(d1, d2));
                float e0=expf(d0-m), e1=expf(d1-m), e2=expf(d2-m);
                float inv = 1.f/(e0+e1+e2);
                x0=e0*inv; x1=e1*inv; x2=e2*inv;
            }
        }
        if (half == 0) { sc0=score; w00=x0; w01=x1; w02=x2; a0i=a; b0i=b; }
        else           { sc1=score; w10=x0; w11=x1; w12=x2; a1i=a; b1i=b; }
    }

    // --- warp softmax over combo scores ---
    float mx = fmaxf(sc0, sc1);
#pragma unroll
    for (int off = 16; off > 0; off >>= 1)
        mx = fmaxf(mx, __shfl_xor_sync(FULLMASK, mx, off));

    if (lane < 9) sCoeff[w][lane] = 0.f;
    __syncwarp();

    if (mx == -INFINITY) {
        if (lane == 0) sCoeff[w][0] = 1.f;     // no valid subset -> y = v[i]
        __syncwarp();
    } else {
        float p0 = (sc0 == -INFINITY) ? 0.f : expf(sc0 - mx);
        float p1 = (sc1 == -INFINITY) ? 0.f : expf(sc1 - mx);
        float s = p0 + p1;
#pragma unroll
        for (int off = 16; off > 0; off >>= 1)
            s += __shfl_xor_sync(FULLMASK, s, off);
        float invs = 1.f / s;
        if (p0 > 0.f) {
            float p = p0 * invs;
            atomicAdd(&sCoeff[w][0],     p * w00);
            atomicAdd(&sCoeff[w][a0i+1], p * w01);
            if (b0i >= 0) atomicAdd(&sCoeff[w][b0i+1], p * w02);
        }
        if (p1 > 0.f) {
            float p = p1 * invs;
            atomicAdd(&sCoeff[w][0],     p * w10);
            atomicAdd(&sCoeff[w][a1i+1], p * w11);
            if (b1i >= 0) atomicAdd(&sCoeff[w][b1i+1], p * w12);
        }
        __syncwarp();
    }

    // --- y = sum_r coeff[r]*v[r] ---
    int bb = head / Hh, h = head - bb*Hh;
    float* ybase = g_y + ((size_t)(bb*Tt + i))*Cc + h*HS;
#pragma unroll
    for (int half = 0; half < 2; half++) {
        int d = lane + (half << 5);
        float y = 0.f;
#pragma unroll
        for (int r = 0; r < 9; r++) y += sCoeff[w][r] * svr[w][r][d];
        ybase[d] = y;
    }
}

// ---------------------------------------------------------------------------
extern "C" void kernel_launch(void* const* d_in, const int* in_sizes, int n_in,
                              void* d_out, int out_size) {
    const float* x      = (const float*)d_in[0];
    const float* W_attn = (const float*)d_in[1];
    const float* b_attn = (const float*)d_in[2];
    const float* W_proj = (const float*)d_in[3];
    const float* b_proj = (const float*)d_in[4];
    float* out = (float*)d_out;

    dim3 blk(256);
    dim3 g1(3*Cc/BN, Bb*Tt/BM);       // 36 x 16
    gemm_qkv_kernel<<<g1, blk>>>(x, W_attn, b_attn);

    dim3 gs(Tt/64, Tt/64, BHn);       // 8 x 8 x 24 (upper blocks early-exit)
    sims_kernel<<<gs, blk>>>();

    dim3 g2(Tt/NW, BHn);              // 64 x 24
    dpp_score_kernel<<<g2, blk>>>();

    dim3 g3(Cc/BN, Bb*Tt/BM);         // 12 x 16
    gemm_proj_kernel<<<g3, blk>>>(W_proj, b_proj, out);
}

// round 9
// speedup vs baseline: 4.3299x; 1.0050x over previous
#include <cuda_runtime.h>
#include <math.h>
#include <stdint.h>

#define Bb 2
#define Tt 512
#define Cc 768
#define Hh 12
#define HS 64
#define BHn (Bb*Hh)

typedef unsigned long long ull;

// scratch (allocation-free rule: __device__ globals)
__device__ float g_q[BHn*Tt*HS];
__device__ float g_k[BHn*Tt*HS];
__device__ float g_v[BHn*Tt*HS];
__device__ float g_y[Bb*Tt*Cc];
__device__ float g_s[(size_t)BHn*Tt*Tt];   // causal sim matrix per head

// lexicographic pairs (a<b) over 8 slots, matching itertools.combinations order
__constant__ int cPA[28] = {0,0,0,0,0,0,0,1,1,1,1,1,1,2,2,2,2,2,3,3,3,3,4,4,4,5,5,6};
__constant__ int cPB[28] = {1,2,3,4,5,6,7,2,3,4,5,6,7,3,4,5,6,7,4,5,6,7,5,6,7,6,7,7};

// 54 dot-tasks: 45 gram pairs (r<=c) + 9 q-dots (c==9 means q)
__constant__ int cTR[54] = {0,0,0,0,0,0,0,0,0, 1,1,1,1,1,1,1,1, 2,2,2,2,2,2,2,
                            3,3,3,3,3,3, 4,4,4,4,4, 5,5,5,5, 6,6,6, 7,7, 8,
                            0,1,2,3,4,5,6,7,8};
__constant__ int cTC[54] = {0,1,2,3,4,5,6,7,8, 1,2,3,4,5,6,7,8, 2,3,4,5,6,7,8,
                            3,4,5,6,7,8, 4,5,6,7,8, 5,6,7,8, 6,7,8, 7,8, 8,
                            9,9,9,9,9,9,9,9,9};

// ---------------------------------------------------------------------------
// packed dual-fp32 FMA helpers (sm_103a FFMA2 via PTX fma.rn.f32x2)
// ---------------------------------------------------------------------------
__device__ __forceinline__ ull pk2(float x) {
    ull r; uint32_t b = __float_as_uint(x);
    asm("mov.b64 %0, {%1, %1};" : "=l"(r) : "r"(b));
    return r;
}
__device__ __forceinline__ void ffma2(ull& acc, ull a, ull b) {
    asm("fma.rn.f32x2 %0, %1, %2, %0;" : "+l"(acc) : "l"(a), "l"(b));
}
__device__ __forceinline__ float lo32(ull v) { return __uint_as_float((uint32_t)v); }
__device__ __forceinline__ float hi32(ull v) { return __uint_as_float((uint32_t)(v >> 32)); }

// ---------------------------------------------------------------------------
// fused QKV GEMM (fp32, FFMA2): C[m,n] = x·W_attnᵀ + b, scatter to g_q/g_k/g_v
// 64x64 tile, 256 threads, 4x4 micro-tile (as 4x2 packed pairs), BK=16
// ---------------------------------------------------------------------------
#define BM 64
#define BN 64
#define BK 16

__global__ void __launch_bounds__(256) gemm_qkv_kernel(
    const float* __restrict__ A,     // x [1024,768]
    const float* __restrict__ Bm,    // W_attn [2304,768]
    const float* __restrict__ bias)  // b_attn [2304]
{
    const int K = Cc;
    __shared__ __align__(16) float As[BK][BM+4];
    __shared__ __align__(16) float Bs[BK][BN+4];
    int tid = threadIdx.x;
    int tx = tid & 15, ty = tid >> 4;
    int m0 = blockIdx.y * BM, n0 = blockIdx.x * BN;
    int lr = tid >> 2;
    int lk = (tid & 3) << 2;
    ull acc2[4][2] = {};
    for (int k0 = 0; k0 < K; k0 += BK) {
        float4 av = *(const float4*)(A  + (size_t)(m0+lr)*K + k0 + lk);
        float4 bv = *(const float4*)(Bm + (size_t)(n0+lr)*K + k0 + lk);
        As[lk+0][lr]=av.x; As[lk+1][lr]=av.y; As[lk+2][lr]=av.z; As[lk+3][lr]=av.w;
        Bs[lk+0][lr]=bv.x; Bs[lk+1][lr]=bv.y; Bs[lk+2][lr]=bv.z; Bs[lk+3][lr]=bv.w;
        __syncthreads();
#pragma unroll
        for (int kk = 0; kk < BK; kk++) {
            float4 a = *(const float4*)&As[kk][ty<<2];
            const ull* bp = (const ull*)&Bs[kk][tx<<2];
            ull b0 = bp[0], b1 = bp[1];
            ull a0 = pk2(a.x), a1 = pk2(a.y), a2 = pk2(a.z), a3 = pk2(a.w);
            ffma2(acc2[0][0], a0, b0); ffma2(acc2[0][1], a0, b1);
            ffma2(acc2[1][0], a1, b0); ffma2(acc2[1][1], a1, b1);
            ffma2(acc2[2][0], a2, b0); ffma2(acc2[2][1], a2, b1);
            ffma2(acc2[3][0], a3, b0); ffma2(acc2[3][1], a3, b1);
        }
        __syncthreads();
    }
#pragma unroll
    for (int im = 0; im < 4; im++) {
#pragma unroll
        for (int jp = 0; jp < 2; jp++) {
#pragma unroll
            for (int e = 0; e < 2; e++) {
                int m = m0 + (ty<<2) + im;
                int n = n0 + (tx<<2) + (jp<<1) + e;
                float val = (e ? hi32(acc2[im][jp]) : lo32(acc2[im][jp])) + bias[n];
                int part = n / Cc;
                int c = n - part*Cc;
                int h = c >> 6;
                int d = c & 63;
                int b = m >> 9;
                int t = m & 511;
                float* dst = (part==0) ? g_q : (part==1) ? g_k : g_v;
                dst[(((size_t)(b*Hh + h))*Tt + t)*HS + d] = val;
            }
        }
    }
}

// ---------------------------------------------------------------------------
// proj GEMM (fp32, FFMA2): out = g_y·W_projᵀ + b  — 64x32 tile, 384 blocks
// ---------------------------------------------------------------------------
#define PM 64
#define PN 32
#define PK 32

__global__ void __launch_bounds__(256) gemm_proj_kernel(
    const float* __restrict__ Bm,    // W_proj [768,768]
    const float* __restrict__ bias,  // b_proj [768]
    float* __restrict__ out)         // [1024,768]
{
    const int K = Cc;
    const float* A = g_y;
    __shared__ __align__(16) float As[PK][PM+4];
    __shared__ __align__(16) float Bs[PK][PN+4];
    int tid = threadIdx.x;
    int tx = tid & 15, ty = tid >> 4;          // tx: 16x2 cols, ty: 16x4 rows
    int m0 = blockIdx.y * PM, n0 = blockIdx.x * PN;
    ull acc2[4] = {};
    for (int k0 = 0; k0 < K; k0 += PK) {
#pragma unroll
        for (int it = 0; it < 2; it++) {
            int f4 = tid + it*256;
            int r = f4 >> 3, c4 = (f4 & 7) << 2;
            float4 v = *(const float4*)(A + (size_t)(m0+r)*K + k0 + c4);
            As[c4+0][r]=v.x; As[c4+1][r]=v.y; As[c4+2][r]=v.z; As[c4+3][r]=v.w;
        }
        {
            int r = tid >> 3, c4 = (tid & 7) << 2;
            float4 v = *(const float4*)(Bm + (size_t)(n0+r)*K + k0 + c4);
            Bs[c4+0][r]=v.x; Bs[c4+1][r]=v.y; Bs[c4+2][r]=v.z; Bs[c4+3][r]=v.w;
        }
        __syncthreads();
#pragma unroll
        for (int kk = 0; kk < PK; kk++) {
            float4 a = *(const float4*)&As[kk][ty<<2];
            ull b = *(const ull*)&Bs[kk][tx<<1];
            ffma2(acc2[0], pk2(a.x), b);
            ffma2(acc2[1], pk2(a.y), b);
            ffma2(acc2[2], pk2(a.z), b);
            ffma2(acc2[3], pk2(a.w), b);
        }
        __syncthreads();
    }
#pragma unroll
    for (int im = 0; im < 4; im++) {
        int m = m0 + (ty<<2) + im;
        int n = n0 + (tx<<1);
        out[(size_t)m*Cc + n  ] = lo32(acc2[im]) + bias[n];
        out[(size_t)m*Cc + n+1] = hi32(acc2[im]) + bias[n+1];
    }
}

// ---------------------------------------------------------------------------
// sims kernel (fp32, FFMA2): S[h][i][j] = q_i·k_j, lower-triangular blocks
// ---------------------------------------------------------------------------
__global__ void __launch_bounds__(256) sims_kernel() {
    if (blockIdx.x > blockIdx.y) return;
    const int head = blockIdx.z;
    const int m0 = blockIdx.y * 64;
    const int n0 = blockIdx.x * 64;
    const float* Qh = g_q + (size_t)head*Tt*HS;
    const float* Kh = g_k + (size_t)head*Tt*HS;
    float* Sh = g_s + (size_t)head*Tt*Tt;

    __shared__ __align__(16) float As[BK][BM+4];
    __shared__ __align__(16) float Bs[BK][BN+4];
    int tid = threadIdx.x;
    int tx = tid & 15, ty = tid >> 4;
    int lr = tid >> 2;
    int lk = (tid & 3) << 2;
    ull acc2[4][2] = {};
    for (int k0 = 0; k0 < HS; k0 += BK) {
        float4 av = *(const float4*)(Qh + (size_t)(m0+lr)*HS + k0 + lk);
        float4 bv = *(const float4*)(Kh + (size_t)(n0+lr)*HS + k0 + lk);
        As[lk+0][lr]=av.x; As[lk+1][lr]=av.y; As[lk+2][lr]=av.z; As[lk+3][lr]=av.w;
        Bs[lk+0][lr]=bv.x; Bs[lk+1][lr]=bv.y; Bs[lk+2][lr]=bv.z; Bs[lk+3][lr]=bv.w;
        __syncthreads();
#pragma unroll
        for (int kk = 0; kk < BK; kk++) {
            float4 a = *(const float4*)&As[kk][ty<<2];
            const ull* bp = (const ull*)&Bs[kk][tx<<2];
            ull b0 = bp[0], b1 = bp[1];
            ull a0 = pk2(a.x), a1 = pk2(a.y), a2 = pk2(a.z), a3 = pk2(a.w);
            ffma2(acc2[0][0], a0, b0); ffma2(acc2[0][1], a0, b1);
            ffma2(acc2[1][0], a1, b0); ffma2(acc2[1][1], a1, b1);
            ffma2(acc2[2][0], a2, b0); ffma2(acc2[2][1], a2, b1);
            ffma2(acc2[3][0], a3, b0); ffma2(acc2[3][1], a3, b1);
        }
        __syncthreads();
    }
#pragma unroll
    for (int im = 0; im < 4; im++) {
#pragma unroll
        for (int jp = 0; jp < 2; jp++) {
            int m = m0 + (ty<<2) + im;
            int n = n0 + (tx<<2) + (jp<<1);
            Sh[(size_t)m*Tt + n  ] = lo32(acc2[im][jp]);
            Sh[(size_t)m*Tt + n+1] = hi32(acc2[im][jp]);
        }
    }
}

// ---------------------------------------------------------------------------
// DPP score kernel: WARP per (token, head). float4 loads throughout.
// ---------------------------------------------------------------------------
#define NW 8
#define FULLMASK 0xffffffffu
#define RS (HS+4)    // row stride in floats (16B aligned rows)

__global__ void __launch_bounds__(256) dpp_score_kernel() {
    const int lane = threadIdx.x & 31;
    const int w    = threadIdx.x >> 5;
    const int i    = blockIdx.x * NW + w;
    const int head = blockIdx.y;

    const float* qh = g_q + (size_t)head*Tt*HS;
    const float* kh = g_k + (size_t)head*Tt*HS;
    const float* vh = g_v + (size_t)head*Tt*HS;
    const float* srow = g_s + ((size_t)head*Tt + i)*Tt;

    __shared__ __align__(16) float skr[NW][10][RS];   // 9 k rows + q row (idx 9)
    __shared__ __align__(16) float svr[NW][9][RS];
    __shared__ float sG[NW][9][9];
    __shared__ float sdv[NW][9];
    __shared__ int   sRows[NW][9];
    __shared__ float sCoeff[NW][9];

    // --- sims row via float4; sv[c4*4+e] <-> j = 4*lane + 128*c4 + e ---
    float sv[16];
#pragma unroll
    for (int c4 = 0; c4 < 4; c4++) {
        float4 t = ((const float4*)srow)[lane + (c4 << 5)];
        int jb = (lane << 2) + (c4 << 7);
        sv[c4*4+0] = (jb+0 <= i) ? t.x : -INFINITY;
        sv[c4*4+1] = (jb+1 <= i) ? t.y : -INFINITY;
        sv[c4*4+2] = (jb+2 <= i) ? t.z : -INFINITY;
        sv[c4*4+3] = (jb+3 <= i) ? t.w : -INFINITY;
    }

    const int ncand = (i + 1 < 8) ? (i + 1) : 8;

    // --- top-8 via warp shfl argmax, min-index tiebreak ---
    int top[8];
#pragma unroll
    for (int r = 0; r < 8; r++) {
        float bv = -INFINITY; int bi = 0x7fffffff;
#pragma unroll
        for (int idx = 0; idx < 16; idx++) {
            int j = (lane << 2) + ((idx >> 2) << 7) + (idx & 3);
            float v = sv[idx];
            if (v > bv || (v == bv && j < bi)) { bv = v; bi = j; }
        }
#pragma unroll
        for (int off = 16; off > 0; off >>= 1) {
            float ov = __shfl_xor_sync(FULLMASK, bv, off);
            int   oi = __shfl_xor_sync(FULLMASK, bi, off);
            if (ov > bv || (ov == bv && oi < bi)) { bv = ov; bi = oi; }
        }
        int sel = bi;
        if (sel < 0 || sel > i) sel = 0;
        top[r] = sel;
        if (((sel >> 2) & 31) == lane)
            sv[((sel >> 7) << 2) | (sel & 3)] = -INFINITY;
    }

    if (lane == 0) {
        sRows[w][0] = i;
#pragma unroll
        for (int r = 0; r < 8; r++) sRows[w][r+1] = top[r];
    }
    __syncwarp();

    // --- stage 9 k rows + 9 v rows + q row, float4 ---
    for (int e = lane; e < 9*16; e += 32) {
        int r = e >> 4, f = e & 15;
        int row = sRows[w][r];
        *(float4*)&skr[w][r][f<<2] = ((const float4*)(kh + (size_t)row*HS))[f];
        *(float4*)&svr[w][r][f<<2] = ((const float4*)(vh + (size_t)row*HS))[f];
    }
    if (lane < 16)
        *(float4*)&skr[w][9][lane<<2] = ((const float4*)(qh + (size_t)i*HS))[lane];
    __syncwarp();

    // --- 54 dot tasks (float4): 45 gram pairs + 9 q-dots ---
    {
        int t0 = lane, t1 = lane + 32;
        int r0 = cTR[t0], c0 = cTC[t0];
        int r1 = (t1 < 54) ? cTR[t1] : 0;
        int c1 = (t1 < 54) ? cTC[t1] : 0;
        float a0 = 0.f, a1 = 0.f;
#pragma unroll
        for (int f = 0; f < 16; f++) {
            float4 x0 = *(const float4*)&skr[w][r0][f<<2];
            float4 y0 = *(const float4*)&skr[w][c0][f<<2];
            a0 += x0.x*y0.x + x0.y*y0.y + x0.z*y0.z + x0.w*y0.w;
            float4 x1 = *(const float4*)&skr[w][r1][f<<2];
            float4 y1 = *(const float4*)&skr[w][c1][f<<2];
            a1 += x1.x*y1.x + x1.y*y1.y + x1.z*y1.z + x1.w*y1.w;
        }
        if (c0 == 9) sdv[w][r0] = a0 * 0.125f;
        else { sG[w][r0][c0] = a0; sG[w][c0][r0] = a0; }
        if (t1 < 54) {
            if (c1 == 9) sdv[w][r1] = a1 * 0.125f;
            else { sG[w][r1][c1] = a1; sG[w][c1][r1] = a1; }
        }
    }
    __syncwarp();

    // --- per-lane combos (lane and lane+32) ---
    float sc0 = -INFINITY, sc1 = -INFINITY;
    float w00=0,w01=0,w02=0, w10=0,w11=0,w12=0;
    int a0i=-1, b0i=-1, a1i=-1, b1i=-1;
#pragma unroll
    for (int half = 0; half < 2; half++) {
        int cid = lane + (half << 5);
        if (cid >= 36) break;
        int a, b, sz;
        if (cid < 8) { sz = 2; a = cid; b = -1; }
        else         { sz = 3; a = cPA[cid-8]; b = cPB[cid-8]; }
        bool valid = (a < ncand) && (sRows[w][a+1] != i);
        if (b >= 0) valid = valid && (b < ncand) && (sRows[w][b+1] != i);
        float score = -INFINITY, x0 = 0.f, x1 = 0.f, x2 = 0.f;
        if (valid) {
            int ra = a + 1;
            if (sz == 2) {
                float det = sG[w][0][0]*sG[w][ra][ra] - sG[w][0][ra]*sG[w][0][ra];
                score = logf(det + 1e-6f) * 0.5f;
                float d0 = sdv[w][0], d1 = sdv[w][ra];
                float m = fmaxf(d0, d1);
                float e0 = expf(d0-m), e1 = expf(d1-m);
                float inv = 1.f/(e0+e1);
                x0 = e0*inv; x1 = e1*inv;
            } else {
                int rb = b + 1;
                float g00=sG[w][0][0],  g01=sG[w][0][ra],  g02=sG[w][0][rb];
                float g11=sG[w][ra][ra], g12=sG[w][ra][rb], g22=sG[w][rb][rb];
                float det = g00*(g11*g22 - g12*g12)
                          - g01*(g01*g22 - g12*g02)
                          + g02*(g01*g12 - g11*g02);
                score = logf(det + 1e-6f) * (1.f/3.f);
                float d0=sdv[w][0], d1=sdv[w][ra], d2=sdv[w][rb];
                float m = fmaxf(d0, fmaxf(d1, d2));
                float e0=expf(d0-m), e1=expf(d1-m), e2=expf(d2-m);
                float inv = 1.f/(e0+e1+e2);
                x0=e0*inv; x1=e1*inv; x2=e2*inv;
            }
        }
        if (half == 0) { sc0=score; w00=x0; w01=x1; w02=x2; a0i=a; b0i=b; }
        else           { sc1=score; w10=x0; w11=x1; w12=x2; a1i=a; b1i=b; }
    }

    // --- warp softmax over combo scores ---
    float mx = fmaxf(sc0, sc1);
#pragma unroll
    for (int off = 16; off > 0; off >>= 1)
        mx = fmaxf(mx, __shfl_xor_sync(FULLMASK, mx, off));

    if (lane < 9) sCoeff[w][lane] = 0.f;
    __syncwarp();

    if (mx == -INFINITY) {
        if (lane == 0) sCoeff[w][0] = 1.f;     // no valid subset -> y = v[i]
        __syncwarp();
    } else {
        float p0 = (sc0 == -INFINITY) ? 0.f : expf(sc0 - mx);
        float p1 = (sc1 == -INFINITY) ? 0.f : expf(sc1 - mx);
        float s = p0 + p1;
#pragma unroll
        for (int off = 16; off > 0; off >>= 1)
            s += __shfl_xor_sync(FULLMASK, s, off);
        float invs = 1.f / s;
        if (p0 > 0.f) {
            float p = p0 * invs;
            atomicAdd(&sCoeff[w][0],     p * w00);
            atomicAdd(&sCoeff[w][a0i+1], p * w01);
            if (b0i >= 0) atomicAdd(&sCoeff[w][b0i+1], p * w02);
        }
        if (p1 > 0.f) {
            float p = p1 * invs;
            atomicAdd(&sCoeff[w][0],     p * w10);
            atomicAdd(&sCoeff[w][a1i+1], p * w11);
            if (b1i >= 0) atomicAdd(&sCoeff[w][b1i+1], p * w12);
        }
        __syncwarp();
    }

    // --- y = sum_r coeff[r]*v[r] ---
    int bb = head / Hh, h = head - bb*Hh;
    float* ybase = g_y + ((size_t)(bb*Tt + i))*Cc + h*HS;
#pragma unroll
    for (int half = 0; half < 2; half++) {
        int d = lane + (half << 5);
        float y = 0.f;
#pragma unroll
        for (int r = 0; r < 9; r++) y += sCoeff[w][r] * svr[w][r][d];
        ybase[d] = y;
    }
}

// ---------------------------------------------------------------------------
extern "C" void kernel_launch(void* const* d_in, const int* in_sizes, int n_in,
                              void* d_out, int out_size) {
    const float* x      = (const float*)d_in[0];
    const float* W_attn = (const float*)d_in[1];
    const float* b_attn = (const float*)d_in[2];
    const float* W_proj = (const float*)d_in[3];
    const float* b_proj = (const float*)d_in[4];
    float* out = (float*)d_out;

    dim3 blk(256);

    dim3 g1(3*Cc/BN, Bb*Tt/BM);       // 36 x 16 = 576 blocks
    gemm_qkv_kernel<<<g1, blk>>>(x, W_attn, b_attn);

    dim3 gs(Tt/64, Tt/64, BHn);       // 8 x 8 x 24 (upper blocks early-exit)
    sims_kernel<<<gs, blk>>>();

    dim3 g2(Tt/NW, BHn);              // 64 x 24
    dpp_score_kernel<<<g2, blk>>>();

    dim3 g3(Cc/PN, Bb*Tt/PM);         // 24 x 16 = 384 blocks
    gemm_proj_kernel<<<g3, blk>>>(W_proj, b_proj, out);
}

// round 12
// speedup vs baseline: 4.3715x; 1.0096x over previous
#include <cuda_runtime.h>
#include <math.h>
#include <stdint.h>

#define Bb 2
#define Tt 512
#define Cc 768
#define Hh 12
#define HS 64
#define BHn (Bb*Hh)

typedef unsigned long long ull;

// scratch (allocation-free rule: __device__ globals)
__device__ float g_q[BHn*Tt*HS];
__device__ float g_k[BHn*Tt*HS];
__device__ float g_v[BHn*Tt*HS];
__device__ float g_y[Bb*Tt*Cc];
__device__ float g_s[(size_t)BHn*Tt*Tt];   // causal sim matrix per head

// lexicographic pairs (a<b) over 8 slots, matching itertools.combinations order
__constant__ int cPA[28] = {0,0,0,0,0,0,0,1,1,1,1,1,1,2,2,2,2,2,3,3,3,3,4,4,4,5,5,6};
__constant__ int cPB[28] = {1,2,3,4,5,6,7,2,3,4,5,6,7,3,4,5,6,7,4,5,6,7,5,6,7,6,7,7};

// 54 dot-tasks: 45 gram pairs (r<=c) + 9 q-dots (c==9 means q)
__constant__ int cTR[54] = {0,0,0,0,0,0,0,0,0, 1,1,1,1,1,1,1,1, 2,2,2,2,2,2,2,
                            3,3,3,3,3,3, 4,4,4,4,4, 5,5,5,5, 6,6,6, 7,7, 8,
                            0,1,2,3,4,5,6,7,8};
__constant__ int cTC[54] = {0,1,2,3,4,5,6,7,8, 1,2,3,4,5,6,7,8, 2,3,4,5,6,7,8,
                            3,4,5,6,7,8, 4,5,6,7,8, 5,6,7,8, 6,7,8, 7,8, 8,
                            9,9,9,9,9,9,9,9,9};

// ---------------------------------------------------------------------------
// packed dual-fp32 FMA helpers
// ---------------------------------------------------------------------------
__device__ __forceinline__ ull pk2(float x) {
    ull r; uint32_t b = __float_as_uint(x);
    asm("mov.b64 %0, {%1, %1};" : "=l"(r) : "r"(b));
    return r;
}
__device__ __forceinline__ void ffma2(ull& acc, ull a, ull b) {
    asm("fma.rn.f32x2 %0, %1, %2, %0;" : "+l"(acc) : "l"(a), "l"(b));
}
__device__ __forceinline__ float lo32(ull v) { return __uint_as_float((uint32_t)v); }
__device__ __forceinline__ float hi32(ull v) { return __uint_as_float((uint32_t)(v >> 32)); }

// ---------------------------------------------------------------------------
// fused QKV GEMM (fp32): C = x·W_attnᵀ + b, scatter to g_q/g_k/g_v
// 64x64 tile, BK=32, 256 threads, 4x4 micro-tile, register double-buffering
// ---------------------------------------------------------------------------
#define BM 64
#define BN 64
#define QBK 32
#define QNC (Cc/QBK)   // 24 chunks

__global__ void __launch_bounds__(256) gemm_qkv_kernel(
    const float* __restrict__ A,     // x [1024,768]
    const float* __restrict__ Bm,    // W_attn [2304,768]
    const float* __restrict__ bias)  // b_attn [2304]
{
    const int K = Cc;
    __shared__ __align__(16) float As[QBK][BM+4];
    __shared__ __align__(16) float Bs[QBK][BN+4];
    int tid = threadIdx.x;
    int tx = tid & 15, ty = tid >> 4;
    int m0 = blockIdx.y * BM, n0 = blockIdx.x * BN;
    // load mapping: 2 float4 per thread per tile
    int lr0 = tid >> 3;                 // rows 0..31
    int lc  = (tid & 7) << 2;           // col 0..28 step 4
    const float* Ap = A  + (size_t)(m0+lr0)*K + lc;
    const float* Bp = Bm + (size_t)(n0+lr0)*K + lc;

    float4 a0, a1, b0, b1;
    a0 = *(const float4*)(Ap);
    a1 = *(const float4*)(Ap + 32*K);
    b0 = *(const float4*)(Bp);
    b1 = *(const float4*)(Bp + 32*K);

    ull acc2[4][2] = {};
    for (int kc = 0; kc < QNC; kc++) {
        // store current chunk (transpose) to smem
        As[lc+0][lr0]=a0.x; As[lc+1][lr0]=a0.y; As[lc+2][lr0]=a0.z; As[lc+3][lr0]=a0.w;
        As[lc+0][lr0+32]=a1.x; As[lc+1][lr0+32]=a1.y; As[lc+2][lr0+32]=a1.z; As[lc+3][lr0+32]=a1.w;
        Bs[lc+0][lr0]=b0.x; Bs[lc+1][lr0]=b0.y; Bs[lc+2][lr0]=b0.z; Bs[lc+3][lr0]=b0.w;
        Bs[lc+0][lr0+32]=b1.x; Bs[lc+1][lr0+32]=b1.y; Bs[lc+2][lr0+32]=b1.z; Bs[lc+3][lr0+32]=b1.w;
        __syncthreads();
        // prefetch next chunk into registers (overlaps with compute below)
        if (kc + 1 < QNC) {
            int k0 = (kc + 1) * QBK;
            a0 = *(const float4*)(Ap + k0);
            a1 = *(const float4*)(Ap + k0 + 32*K);
            b0 = *(const float4*)(Bp + k0);
            b1 = *(const float4*)(Bp + k0 + 32*K);
        }
#pragma unroll
        for (int kk = 0; kk < QBK; kk++) {
            float4 a = *(const float4*)&As[kk][ty<<2];
            const ull* bp = (const ull*)&Bs[kk][tx<<2];
            ull bb0 = bp[0], bb1 = bp[1];
            ull p0 = pk2(a.x), p1 = pk2(a.y), p2 = pk2(a.z), p3 = pk2(a.w);
            ffma2(acc2[0][0], p0, bb0); ffma2(acc2[0][1], p0, bb1);
            ffma2(acc2[1][0], p1, bb0); ffma2(acc2[1][1], p1, bb1);
            ffma2(acc2[2][0], p2, bb0); ffma2(acc2[2][1], p2, bb1);
            ffma2(acc2[3][0], p3, bb0); ffma2(acc2[3][1], p3, bb1);
        }
        __syncthreads();
    }
#pragma unroll
    for (int im = 0; im < 4; im++) {
#pragma unroll
        for (int jp = 0; jp < 2; jp++) {
#pragma unroll
            for (int e = 0; e < 2; e++) {
                int m = m0 + (ty<<2) + im;
                int n = n0 + (tx<<2) + (jp<<1) + e;
                float val = (e ? hi32(acc2[im][jp]) : lo32(acc2[im][jp])) + bias[n];
                int part = n / Cc;
                int c = n - part*Cc;
                int h = c >> 6;
                int d = c & 63;
                int b = m >> 9;
                int t = m & 511;
                float* dst = (part==0) ? g_q : (part==1) ? g_k : g_v;
                dst[(((size_t)(b*Hh + h))*Tt + t)*HS + d] = val;
            }
        }
    }
}

// ---------------------------------------------------------------------------
// proj GEMM (fp32): out = g_y·W_projᵀ + b — 64x32 tile, BK=32, reg dbl-buffer
// ---------------------------------------------------------------------------
#define PM 64
#define PN 32
#define PK 32
#define PNC (Cc/PK)

__global__ void __launch_bounds__(256) gemm_proj_kernel(
    const float* __restrict__ Bm,    // W_proj [768,768]
    const float* __restrict__ bias,  // b_proj [768]
    float* __restrict__ out)         // [1024,768]
{
    const int K = Cc;
    const float* A = g_y;
    __shared__ __align__(16) float As[PK][PM+4];
    __shared__ __align__(16) float Bs[PK][PN+4];
    int tid = threadIdx.x;
    int tx = tid & 15, ty = tid >> 4;
    int m0 = blockIdx.y * PM, n0 = blockIdx.x * PN;
    // A: 64x32 = 512 f4 -> 2 per thread ; B: 32x32 = 256 f4 -> 1 per thread
    int ar = tid >> 3;                  // 0..31
    int ac = (tid & 7) << 2;
    int br = tid >> 3;
    const float* Ap = A  + (size_t)(m0+ar)*K + ac;
    const float* Bp = Bm + (size_t)(n0+(br&31))*K + ac;
    bool bload = (tid < 256);           // B needs exactly 256 f4? 32 rows x 8 cols = 256 -> all threads
    float4 a0, a1, b0;
    a0 = *(const float4*)(Ap);
    a1 = *(const float4*)(Ap + 32*K);
    b0 = *(const float4*)(Bp);

    ull acc2[4] = {};
    for (int kc = 0; kc < PNC; kc++) {
        As[ac+0][ar]=a0.x; As[ac+1][ar]=a0.y; As[ac+2][ar]=a0.z; As[ac+3][ar]=a0.w;
        As[ac+0][ar+32]=a1.x; As[ac+1][ar+32]=a1.y; As[ac+2][ar+32]=a1.z; As[ac+3][ar+32]=a1.w;
        if (bload) {
            Bs[ac+0][br]=b0.x; Bs[ac+1][br]=b0.y; Bs[ac+2][br]=b0.z; Bs[ac+3][br]=b0.w;
        }
        __syncthreads();
        if (kc + 1 < PNC) {
            int k0 = (kc + 1) * PK;
            a0 = *(const float4*)(Ap + k0);
            a1 = *(const float4*)(Ap + k0 + 32*K);
            b0 = *(const float4*)(Bp + k0);
        }
#pragma unroll
        for (int kk = 0; kk < PK; kk++) {
            float4 a = *(const float4*)&As[kk][ty<<2];
            ull b = *(const ull*)&Bs[kk][tx<<1];
            ffma2(acc2[0], pk2(a.x), b);
            ffma2(acc2[1], pk2(a.y), b);
            ffma2(acc2[2], pk2(a.z), b);
            ffma2(acc2[3], pk2(a.w), b);
        }
        __syncthreads();
    }
#pragma unroll
    for (int im = 0; im < 4; im++) {
        int m = m0 + (ty<<2) + im;
        int n = n0 + (tx<<1);
        out[(size_t)m*Cc + n  ] = lo32(acc2[im]) + bias[n];
        out[(size_t)m*Cc + n+1] = hi32(acc2[im]) + bias[n+1];
    }
}

// ---------------------------------------------------------------------------
// sims kernel (fp32, FFMA2): S[h][i][j] = q_i·k_j, lower-triangular blocks
// ---------------------------------------------------------------------------
#define SBK 16

__global__ void __launch_bounds__(256) sims_kernel() {
    if (blockIdx.x > blockIdx.y) return;
    const int head = blockIdx.z;
    const int m0 = blockIdx.y * 64;
    const int n0 = blockIdx.x * 64;
    const float* Qh = g_q + (size_t)head*Tt*HS;
    const float* Kh = g_k + (size_t)head*Tt*HS;
    float* Sh = g_s + (size_t)head*Tt*Tt;

    __shared__ __align__(16) float As[SBK][BM+4];
    __shared__ __align__(16) float Bs[SBK][BN+4];
    int tid = threadIdx.x;
    int tx = tid & 15, ty = tid >> 4;
    int lr = tid >> 2;
    int lk = (tid & 3) << 2;
    ull acc2[4][2] = {};
    for (int k0 = 0; k0 < HS; k0 += SBK) {
        float4 av = *(const float4*)(Qh + (size_t)(m0+lr)*HS + k0 + lk);
        float4 bv = *(const float4*)(Kh + (size_t)(n0+lr)*HS + k0 + lk);
        As[lk+0][lr]=av.x; As[lk+1][lr]=av.y; As[lk+2][lr]=av.z; As[lk+3][lr]=av.w;
        Bs[lk+0][lr]=bv.x; Bs[lk+1][lr]=bv.y; Bs[lk+2][lr]=bv.z; Bs[lk+3][lr]=bv.w;
        __syncthreads();
#pragma unroll
        for (int kk = 0; kk < SBK; kk++) {
            float4 a = *(const float4*)&As[kk][ty<<2];
            const ull* bp = (const ull*)&Bs[kk][tx<<2];
            ull b0 = bp[0], b1 = bp[1];
            ull a0 = pk2(a.x), a1 = pk2(a.y), a2 = pk2(a.z), a3 = pk2(a.w);
            ffma2(acc2[0][0], a0, b0); ffma2(acc2[0][1], a0, b1);
            ffma2(acc2[1][0], a1, b0); ffma2(acc2[1][1], a1, b1);
            ffma2(acc2[2][0], a2, b0); ffma2(acc2[2][1], a2, b1);
            ffma2(acc2[3][0], a3, b0); ffma2(acc2[3][1], a3, b1);
        }
        __syncthreads();
    }
#pragma unroll
    for (int im = 0; im < 4; im++) {
#pragma unroll
        for (int jp = 0; jp < 2; jp++) {
            int m = m0 + (ty<<2) + im;
            int n = n0 + (tx<<2) + (jp<<1);
            Sh[(size_t)m*Tt + n  ] = lo32(acc2[im][jp]);
            Sh[(size_t)m*Tt + n+1] = hi32(acc2[im][jp]);
        }
    }
}

// ---------------------------------------------------------------------------
// DPP score kernel: WARP per (token, head). float4 loads throughout.
// ---------------------------------------------------------------------------
#define NW 8
#define FULLMASK 0xffffffffu
#define RS (HS+4)

__global__ void __launch_bounds__(256) dpp_score_kernel() {
    const int lane = threadIdx.x & 31;
    const int w    = threadIdx.x >> 5;
    const int i    = blockIdx.x * NW + w;
    const int head = blockIdx.y;

    const float* qh = g_q + (size_t)head*Tt*HS;
    const float* kh = g_k + (size_t)head*Tt*HS;
    const float* vh = g_v + (size_t)head*Tt*HS;
    const float* srow = g_s + ((size_t)head*Tt + i)*Tt;

    __shared__ __align__(16) float skr[NW][10][RS];
    __shared__ __align__(16) float svr[NW][9][RS];
    __shared__ float sG[NW][9][9];
    __shared__ float sdv[NW][9];
    __shared__ int   sRows[NW][9];
    __shared__ float sCoeff[NW][9];

    float sv[16];
#pragma unroll
    for (int c4 = 0; c4 < 4; c4++) {
        float4 t = ((const float4*)srow)[lane + (c4 << 5)];
        int jb = (lane << 2) + (c4 << 7);
        sv[c4*4+0] = (jb+0 <= i) ? t.x : -INFINITY;
        sv[c4*4+1] = (jb+1 <= i) ? t.y : -INFINITY;
        sv[c4*4+2] = (jb+2 <= i) ? t.z : -INFINITY;
        sv[c4*4+3] = (jb+3 <= i) ? t.w : -INFINITY;
    }

    const int ncand = (i + 1 < 8) ? (i + 1) : 8;

    int top[8];
#pragma unroll
    for (int r = 0; r < 8; r++) {
        float bv = -INFINITY; int bi = 0x7fffffff;
#pragma unroll
        for (int idx = 0; idx < 16; idx++) {
            int j = (lane << 2) + ((idx >> 2) << 7) + (idx & 3);
            float v = sv[idx];
            if (v > bv || (v == bv && j < bi)) { bv = v; bi = j; }
        }
#pragma unroll
        for (int off = 16; off > 0; off >>= 1) {
            float ov = __shfl_xor_sync(FULLMASK, bv, off);
            int   oi = __shfl_xor_sync(FULLMASK, bi, off);
            if (ov > bv || (ov == bv && oi < bi)) { bv = ov; bi = oi; }
        }
        int sel = bi;
        if (sel < 0 || sel > i) sel = 0;
        top[r] = sel;
        if (((sel >> 2) & 31) == lane)
            sv[((sel >> 7) << 2) | (sel & 3)] = -INFINITY;
    }

    if (lane == 0) {
        sRows[w][0] = i;
#pragma unroll
        for (int r = 0; r < 8; r++) sRows[w][r+1] = top[r];
    }
    __syncwarp();

    for (int e = lane; e < 9*16; e += 32) {
        int r = e >> 4, f = e & 15;
        int row = sRows[w][r];
        *(float4*)&skr[w][r][f<<2] = ((const float4*)(kh + (size_t)row*HS))[f];
        *(float4*)&svr[w][r][f<<2] = ((const float4*)(vh + (size_t)row*HS))[f];
    }
    if (lane < 16)
        *(float4*)&skr[w][9][lane<<2] = ((const float4*)(qh + (size_t)i*HS))[lane];
    __syncwarp();

    {
        int t0 = lane, t1 = lane + 32;
        int r0 = cTR[t0], c0 = cTC[t0];
        int r1 = (t1 < 54) ? cTR[t1] : 0;
        int c1 = (t1 < 54) ? cTC[t1] : 0;
        float a0 = 0.f, a1 = 0.f;
#pragma unroll
        for (int f = 0; f < 16; f++) {
            float4 x0 = *(const float4*)&skr[w][r0][f<<2];
            float4 y0 = *(const float4*)&skr[w][c0][f<<2];
            a0 += x0.x*y0.x + x0.y*y0.y + x0.z*y0.z + x0.w*y0.w;
            float4 x1 = *(const float4*)&skr[w][r1][f<<2];
            float4 y1 = *(const float4*)&skr[w][c1][f<<2];
            a1 += x1.x*y1.x + x1.y*y1.y + x1.z*y1.z + x1.w*y1.w;
        }
        if (c0 == 9) sdv[w][r0] = a0 * 0.125f;
        else { sG[w][r0][c0] = a0; sG[w][c0][r0] = a0; }
        if (t1 < 54) {
            if (c1 == 9) sdv[w][r1] = a1 * 0.125f;
            else { sG[w][r1][c1] = a1; sG[w][c1][r1] = a1; }
        }
    }
    __syncwarp();

    float sc0 = -INFINITY, sc1 = -INFINITY;
    float w00=0,w01=0,w02=0, w10=0,w11=0,w12=0;
    int a0i=-1, b0i=-1, a1i=-1, b1i=-1;
#pragma unroll
    for (int half = 0; half < 2; half++) {
        int cid = lane + (half << 5);
        if (cid >= 36) break;
        int a, b, sz;
        if (cid < 8) { sz = 2; a = cid; b = -1; }
        else         { sz = 3; a = cPA[cid-8]; b = cPB[cid-8]; }
        bool valid = (a < ncand) && (sRows[w][a+1] != i);
        if (b >= 0) valid = valid && (b < ncand) && (sRows[w][b+1] != i);
        float score = -INFINITY, x0 = 0.f, x1 = 0.f, x2 = 0.f;
        if (valid) {
            int ra = a + 1;
            if (sz == 2) {
                float det = sG[w][0][0]*sG[w][ra][ra] - sG[w][0][ra]*sG[w][0][ra];
                score = logf(det + 1e-6f) * 0.5f;
                float d0 = sdv[w][0], d1 = sdv[w][ra];
                float m = fmaxf(d0, d1);
                float e0 = expf(d0-m), e1 = expf(d1-m);
                float inv = 1.f/(e0+e1);
                x0 = e0*inv; x1 = e1*inv;
            } else {
                int rb = b + 1;
                float g00=sG[w][0][0],  g01=sG[w][0][ra],  g02=sG[w][0][rb];
                float g11=sG[w][ra][ra], g12=sG[w][ra][rb], g22=sG[w][rb][rb];
                float det = g00*(g11*g22 - g12*g12)
                          - g01*(g01*g22 - g12*g02)
                          + g02*(g01*g12 - g11*g02);
                score = logf(det + 1e-6f) * (1.f/3.f);
                float d0=sdv[w][0], d1=sdv[w][ra], d2=sdv[w][rb];
                float m = fmaxf(d0, fmaxf(d1, d2));
                float e0=expf(d0-m), e1=expf(d1-m), e2=expf(d2-m);
                float inv = 1.f/(e0+e1+e2);
                x0=e0*inv; x1=e1*inv; x2=e2*inv;
            }
        }
        if (half == 0) { sc0=score; w00=x0; w01=x1; w02=x2; a0i=a; b0i=b; }
        else           { sc1=score; w10=x0; w11=x1; w12=x2; a1i=a; b1i=b; }
    }

    float mx = fmaxf(sc0, sc1);
#pragma unroll
    for (int off = 16; off > 0; off >>= 1)
        mx = fmaxf(mx, __shfl_xor_sync(FULLMASK, mx, off));

    if (lane < 9) sCoeff[w][lane] = 0.f;
    __syncwarp();

    if (mx == -INFINITY) {
        if (lane == 0) sCoeff[w][0] = 1.f;
        __syncwarp();
    } else {
        float p0 = (sc0 == -INFINITY) ? 0.f : expf(sc0 - mx);
        float p1 = (sc1 == -INFINITY) ? 0.f : expf(sc1 - mx);
        float s = p0 + p1;
#pragma unroll
        for (int off = 16; off > 0; off >>= 1)
            s += __shfl_xor_sync(FULLMASK, s, off);
        float invs = 1.f / s;
        if (p0 > 0.f) {
            float p = p0 * invs;
            atomicAdd(&sCoeff[w][0],     p * w00);
            atomicAdd(&sCoeff[w][a0i+1], p * w01);
            if (b0i >= 0) atomicAdd(&sCoeff[w][b0i+1], p * w02);
        }
        if (p1 > 0.f) {
            float p = p1 * invs;
            atomicAdd(&sCoeff[w][0],     p * w10);
            atomicAdd(&sCoeff[w][a1i+1], p * w11);
            if (b1i >= 0) atomicAdd(&sCoeff[w][b1i+1], p * w12);
        }
        __syncwarp();
    }

    int bb = head / Hh, h = head - bb*Hh;
    float* ybase = g_y + ((size_t)(bb*Tt + i))*Cc + h*HS;
#pragma unroll
    for (int half = 0; half < 2; half++) {
        int d = lane + (half << 5);
        float y = 0.f;
#pragma unroll
        for (int r = 0; r < 9; r++) y += sCoeff[w][r] * svr[w][r][d];
        ybase[d] = y;
    }
}

// ---------------------------------------------------------------------------
extern "C" void kernel_launch(void* const* d_in, const int* in_sizes, int n_in,
                              void* d_out, int out_size) {
    const float* x      = (const float*)d_in[0];
    const float* W_attn = (const float*)d_in[1];
    const float* b_attn = (const float*)d_in[2];
    const float* W_proj = (const float*)d_in[3];
    const float* b_proj = (const float*)d_in[4];
    float* out = (float*)d_out;

    dim3 blk(256);

    dim3 g1(3*Cc/BN, Bb*Tt/BM);       // 36 x 16 = 576 blocks
    gemm_qkv_kernel<<<g1, blk>>>(x, W_attn, b_attn);

    dim3 gs(Tt/64, Tt/64, BHn);       // 8 x 8 x 24 (upper blocks early-exit)
    sims_kernel<<<gs, blk>>>();

    dim3 g2(Tt/NW, BHn);              // 64 x 24
    dpp_score_kernel<<<g2, blk>>>();

    dim3 g3(Cc/PN, Bb*Tt/PM);         // 24 x 16 = 384 blocks
    gemm_proj_kernel<<<g3, blk>>>(W_proj, b_proj, out);
}

// round 13
// speedup vs baseline: 5.2134x; 1.1926x over previous
#include <cuda_runtime.h>
#include <math.h>
#include <stdint.h>

#define Bb 2
#define Tt 512
#define Cc 768
#define Hh 12
#define HS 64
#define BHn (Bb*Hh)

typedef unsigned long long ull;

// scratch (allocation-free rule: __device__ globals)
__device__ float g_q[BHn*Tt*HS];
__device__ float g_k[BHn*Tt*HS];
__device__ float g_v[BHn*Tt*HS];
__device__ float g_y[Bb*Tt*Cc];
__device__ float g_s[(size_t)BHn*Tt*Tt];   // causal sim matrix per head

// lexicographic pairs (a<b) over 8 slots, matching itertools.combinations order
__constant__ int cPA[28] = {0,0,0,0,0,0,0,1,1,1,1,1,1,2,2,2,2,2,3,3,3,3,4,4,4,5,5,6};
__constant__ int cPB[28] = {1,2,3,4,5,6,7,2,3,4,5,6,7,3,4,5,6,7,4,5,6,7,5,6,7,6,7,7};

// 54 dot-tasks: 45 gram pairs (r<=c) + 9 q-dots (c==9 means q)
__constant__ int cTR[54] = {0,0,0,0,0,0,0,0,0, 1,1,1,1,1,1,1,1, 2,2,2,2,2,2,2,
                            3,3,3,3,3,3, 4,4,4,4,4, 5,5,5,5, 6,6,6, 7,7, 8,
                            0,1,2,3,4,5,6,7,8};
__constant__ int cTC[54] = {0,1,2,3,4,5,6,7,8, 1,2,3,4,5,6,7,8, 2,3,4,5,6,7,8,
                            3,4,5,6,7,8, 4,5,6,7,8, 5,6,7,8, 6,7,8, 7,8, 8,
                            9,9,9,9,9,9,9,9,9};

// ---------------------------------------------------------------------------
// packed dual-fp32 FMA helpers (used in sims kernel only)
// ---------------------------------------------------------------------------
__device__ __forceinline__ ull pk2(float x) {
    ull r; uint32_t b = __float_as_uint(x);
    asm("mov.b64 %0, {%1, %1};" : "=l"(r) : "r"(b));
    return r;
}
__device__ __forceinline__ void ffma2(ull& acc, ull a, ull b) {
    asm("fma.rn.f32x2 %0, %1, %2, %0;" : "+l"(acc) : "l"(a), "l"(b));
}
__device__ __forceinline__ float lo32(ull v) { return __uint_as_float((uint32_t)v); }
__device__ __forceinline__ float hi32(ull v) { return __uint_as_float((uint32_t)(v >> 32)); }

// ---------------------------------------------------------------------------
// fused QKV GEMM (fp32): C = x·W_attnᵀ + b, scatter to g_q/g_k/g_v
// 128x128 tile, 256 threads, 8x8 micro-tile (split 4+4 rows/cols), BK=16,
// smem double-buffer + register-staged global prefetch (1 sync per chunk)
// ---------------------------------------------------------------------------
#define QBM 128
#define QBN 128
#define QBK 16
#define QNC (Cc/QBK)   // 48

__global__ void __launch_bounds__(256) gemm_qkv_kernel(
    const float* __restrict__ A,     // x [1024,768]
    const float* __restrict__ Bm,    // W_attn [2304,768]
    const float* __restrict__ bias)  // b_attn [2304]
{
    const int K = Cc;
    __shared__ __align__(16) float As[2][QBK][QBM+4];
    __shared__ __align__(16) float Bs[2][QBK][QBN+4];
    const int tid = threadIdx.x;
    const int tx = tid & 15, ty = tid >> 4;
    const int m0 = blockIdx.y * QBM, n0 = blockIdx.x * QBN;

    const int lr = tid >> 2;            // 0..63 (rows; +64 for second half)
    const int lc = (tid & 3) << 2;      // 0,4,8,12
    const float* Ap = A  + (size_t)(m0 + lr)*K + lc;
    const float* Bp = Bm + (size_t)(n0 + lr)*K + lc;

    float4 ra0, ra1, rb0, rb1;
    ra0 = *(const float4*)(Ap);
    ra1 = *(const float4*)(Ap + (size_t)64*K);
    rb0 = *(const float4*)(Bp);
    rb1 = *(const float4*)(Bp + (size_t)64*K);
    // store chunk 0 into buffer 0
    {
        As[0][lc+0][lr]=ra0.x; As[0][lc+1][lr]=ra0.y; As[0][lc+2][lr]=ra0.z; As[0][lc+3][lr]=ra0.w;
        As[0][lc+0][64+lr]=ra1.x; As[0][lc+1][64+lr]=ra1.y; As[0][lc+2][64+lr]=ra1.z; As[0][lc+3][64+lr]=ra1.w;
        Bs[0][lc+0][lr]=rb0.x; Bs[0][lc+1][lr]=rb0.y; Bs[0][lc+2][lr]=rb0.z; Bs[0][lc+3][lr]=rb0.w;
        Bs[0][lc+0][64+lr]=rb1.x; Bs[0][lc+1][64+lr]=rb1.y; Bs[0][lc+2][64+lr]=rb1.z; Bs[0][lc+3][64+lr]=rb1.w;
    }
    __syncthreads();

    float acc[8][8];
#pragma unroll
    for (int i=0;i<8;i++)
#pragma unroll
      for (int j=0;j<8;j++) acc[i][j]=0.f;

    int cur = 0;
    for (int kc = 0; kc < QNC; kc++) {
        if (kc + 1 < QNC) {
            int k0 = (kc + 1) * QBK;
            ra0 = *(const float4*)(Ap + k0);
            ra1 = *(const float4*)(Ap + (size_t)64*K + k0);
            rb0 = *(const float4*)(Bp + k0);
            rb1 = *(const float4*)(Bp + (size_t)64*K + k0);
        }
#pragma unroll
        for (int kk = 0; kk < QBK; kk++) {
            float4 a0 = *(const float4*)&As[cur][kk][ty<<2];
            float4 a1 = *(const float4*)&As[cur][kk][64+(ty<<2)];
            float4 b0 = *(const float4*)&Bs[cur][kk][tx<<2];
            float4 b1 = *(const float4*)&Bs[cur][kk][64+(tx<<2)];
            float av[8] = {a0.x,a0.y,a0.z,a0.w, a1.x,a1.y,a1.z,a1.w};
            float bv[8] = {b0.x,b0.y,b0.z,b0.w, b1.x,b1.y,b1.z,b1.w};
#pragma unroll
            for (int i = 0; i < 8; i++)
#pragma unroll
                for (int j = 0; j < 8; j++)
                    acc[i][j] += av[i]*bv[j];
        }
        if (kc + 1 < QNC) {
            int nb = cur ^ 1;
            As[nb][lc+0][lr]=ra0.x; As[nb][lc+1][lr]=ra0.y; As[nb][lc+2][lr]=ra0.z; As[nb][lc+3][lr]=ra0.w;
            As[nb][lc+0][64+lr]=ra1.x; As[nb][lc+1][64+lr]=ra1.y; As[nb][lc+2][64+lr]=ra1.z; As[nb][lc+3][64+lr]=ra1.w;
            Bs[nb][lc+0][lr]=rb0.x; Bs[nb][lc+1][lr]=rb0.y; Bs[nb][lc+2][lr]=rb0.z; Bs[nb][lc+3][lr]=rb0.w;
            Bs[nb][lc+0][64+lr]=rb1.x; Bs[nb][lc+1][64+lr]=rb1.y; Bs[nb][lc+2][64+lr]=rb1.z; Bs[nb][lc+3][64+lr]=rb1.w;
        }
        __syncthreads();
        cur ^= 1;
    }

    // epilogue: scatter 8x8 outputs
#pragma unroll
    for (int im = 0; im < 8; im++) {
        int m = m0 + ((im < 4) ? ((ty<<2) + im) : (64 + (ty<<2) + im - 4));
        int b = m >> 9, t = m & 511;
#pragma unroll
        for (int jn = 0; jn < 8; jn++) {
            int n = n0 + ((jn < 4) ? ((tx<<2) + jn) : (64 + (tx<<2) + jn - 4));
            float val = acc[im][jn] + bias[n];
            int part = n / Cc;
            int c = n - part*Cc;
            int h = c >> 6;
            int d = c & 63;
            float* dst = (part==0) ? g_q : (part==1) ? g_k : g_v;
            dst[(((size_t)(b*Hh + h))*Tt + t)*HS + d] = val;
        }
    }
}

// ---------------------------------------------------------------------------
// proj GEMM (fp32): out = g_y·W_projᵀ + b
// 64x64 tile, 128 threads, 8x4 micro-tile (split 4+4 rows), BK=16,
// smem double-buffer + register-staged prefetch. 192 blocks.
// ---------------------------------------------------------------------------
#define PBM 64
#define PBN 64
#define PBK 16
#define PNC (Cc/PBK)   // 48

__global__ void __launch_bounds__(128) gemm_proj_kernel(
    const float* __restrict__ Bm,    // W_proj [768,768]
    const float* __restrict__ bias,  // b_proj [768]
    float* __restrict__ out)         // [1024,768]
{
    const int K = Cc;
    const float* A = g_y;
    __shared__ __align__(16) float As[2][PBK][PBM+4];
    __shared__ __align__(16) float Bs[2][PBK][PBN+4];
    const int tid = threadIdx.x;
    const int tx = tid & 15, ty = tid >> 4;     // ty 0..7
    const int m0 = blockIdx.y * PBM, n0 = blockIdx.x * PBN;

    const int lr = tid >> 2;            // 0..31 (+32 second half)
    const int lc = (tid & 3) << 2;
    const float* Ap = A  + (size_t)(m0 + lr)*K + lc;
    const float* Bp = Bm + (size_t)(n0 + lr)*K + lc;

    float4 ra0, ra1, rb0, rb1;
    ra0 = *(const float4*)(Ap);
    ra1 = *(const float4*)(Ap + (size_t)32*K);
    rb0 = *(const float4*)(Bp);
    rb1 = *(const float4*)(Bp + (size_t)32*K);
    {
        As[0][lc+0][lr]=ra0.x; As[0][lc+1][lr]=ra0.y; As[0][lc+2][lr]=ra0.z; As[0][lc+3][lr]=ra0.w;
        As[0][lc+0][32+lr]=ra1.x; As[0][lc+1][32+lr]=ra1.y; As[0][lc+2][32+lr]=ra1.z; As[0][lc+3][32+lr]=ra1.w;
        Bs[0][lc+0][lr]=rb0.x; Bs[0][lc+1][lr]=rb0.y; Bs[0][lc+2][lr]=rb0.z; Bs[0][lc+3][lr]=rb0.w;
        Bs[0][lc+0][32+lr]=rb1.x; Bs[0][lc+1][32+lr]=rb1.y; Bs[0][lc+2][32+lr]=rb1.z; Bs[0][lc+3][32+lr]=rb1.w;
    }
    __syncthreads();

    float acc[8][4];
#pragma unroll
    for (int i=0;i<8;i++)
#pragma unroll
      for (int j=0;j<4;j++) acc[i][j]=0.f;

    int cur = 0;
    for (int kc = 0; kc < PNC; kc++) {
        if (kc + 1 < PNC) {
            int k0 = (kc + 1) * PBK;
            ra0 = *(const float4*)(Ap + k0);
            ra1 = *(const float4*)(Ap + (size_t)32*K + k0);
            rb0 = *(const float4*)(Bp + k0);
            rb1 = *(const float4*)(Bp + (size_t)32*K + k0);
        }
#pragma unroll
        for (int kk = 0; kk < PBK; kk++) {
            float4 a0 = *(const float4*)&As[cur][kk][ty<<2];
            float4 a1 = *(const float4*)&As[cur][kk][32+(ty<<2)];
            float4 b  = *(const float4*)&Bs[cur][kk][tx<<2];
            float av[8] = {a0.x,a0.y,a0.z,a0.w, a1.x,a1.y,a1.z,a1.w};
#pragma unroll
            for (int i = 0; i < 8; i++) {
                acc[i][0] += av[i]*b.x;
                acc[i][1] += av[i]*b.y;
                acc[i][2] += av[i]*b.z;
                acc[i][3] += av[i]*b.w;
            }
        }
        if (kc + 1 < PNC) {
            int nb = cur ^ 1;
            As[nb][lc+0][lr]=ra0.x; As[nb][lc+1][lr]=ra0.y; As[nb][lc+2][lr]=ra0.z; As[nb][lc+3][lr]=ra0.w;
            As[nb][lc+0][32+lr]=ra1.x; As[nb][lc+1][32+lr]=ra1.y; As[nb][lc+2][32+lr]=ra1.z; As[nb][lc+3][32+lr]=ra1.w;
            Bs[nb][lc+0][lr]=rb0.x; Bs[nb][lc+1][lr]=rb0.y; Bs[nb][lc+2][lr]=rb0.z; Bs[nb][lc+3][lr]=rb0.w;
            Bs[nb][lc+0][32+lr]=rb1.x; Bs[nb][lc+1][32+lr]=rb1.y; Bs[nb][lc+2][32+lr]=rb1.z; Bs[nb][lc+3][32+lr]=rb1.w;
        }
        __syncthreads();
        cur ^= 1;
    }

#pragma unroll
    for (int im = 0; im < 8; im++) {
        int m = m0 + ((im < 4) ? ((ty<<2) + im) : (32 + (ty<<2) + im - 4));
        int n = n0 + (tx<<2);
        float* dst = out + (size_t)m*Cc + n;
        dst[0] = acc[im][0] + bias[n+0];
        dst[1] = acc[im][1] + bias[n+1];
        dst[2] = acc[im][2] + bias[n+2];
        dst[3] = acc[im][3] + bias[n+3];
    }
}

// ---------------------------------------------------------------------------
// sims kernel (fp32, FFMA2): S[h][i][j] = q_i·k_j, lower-triangular blocks
// ---------------------------------------------------------------------------
#define SBK 16
#define SBM 64
#define SBN 64

__global__ void __launch_bounds__(256) sims_kernel() {
    if (blockIdx.x > blockIdx.y) return;
    const int head = blockIdx.z;
    const int m0 = blockIdx.y * 64;
    const int n0 = blockIdx.x * 64;
    const float* Qh = g_q + (size_t)head*Tt*HS;
    const float* Kh = g_k + (size_t)head*Tt*HS;
    float* Sh = g_s + (size_t)head*Tt*Tt;

    __shared__ __align__(16) float As[SBK][SBM+4];
    __shared__ __align__(16) float Bs[SBK][SBN+4];
    int tid = threadIdx.x;
    int tx = tid & 15, ty = tid >> 4;
    int lr = tid >> 2;
    int lk = (tid & 3) << 2;
    ull acc2[4][2] = {};
    for (int k0 = 0; k0 < HS; k0 += SBK) {
        float4 av = *(const float4*)(Qh + (size_t)(m0+lr)*HS + k0 + lk);
        float4 bv = *(const float4*)(Kh + (size_t)(n0+lr)*HS + k0 + lk);
        As[lk+0][lr]=av.x; As[lk+1][lr]=av.y; As[lk+2][lr]=av.z; As[lk+3][lr]=av.w;
        Bs[lk+0][lr]=bv.x; Bs[lk+1][lr]=bv.y; Bs[lk+2][lr]=bv.z; Bs[lk+3][lr]=bv.w;
        __syncthreads();
#pragma unroll
        for (int kk = 0; kk < SBK; kk++) {
            float4 a = *(const float4*)&As[kk][ty<<2];
            const ull* bp = (const ull*)&Bs[kk][tx<<2];
            ull b0 = bp[0], b1 = bp[1];
            ull a0 = pk2(a.x), a1 = pk2(a.y), a2 = pk2(a.z), a3 = pk2(a.w);
            ffma2(acc2[0][0], a0, b0); ffma2(acc2[0][1], a0, b1);
            ffma2(acc2[1][0], a1, b0); ffma2(acc2[1][1], a1, b1);
            ffma2(acc2[2][0], a2, b0); ffma2(acc2[2][1], a2, b1);
            ffma2(acc2[3][0], a3, b0); ffma2(acc2[3][1], a3, b1);
        }
        __syncthreads();
    }
#pragma unroll
    for (int im = 0; im < 4; im++) {
#pragma unroll
        for (int jp = 0; jp < 2; jp++) {
            int m = m0 + (ty<<2) + im;
            int n = n0 + (tx<<2) + (jp<<1);
            Sh[(size_t)m*Tt + n  ] = lo32(acc2[im][jp]);
            Sh[(size_t)m*Tt + n+1] = hi32(acc2[im][jp]);
        }
    }
}

// ---------------------------------------------------------------------------
// DPP score kernel: WARP per (token, head). float4 loads throughout.
// ---------------------------------------------------------------------------
#define NW 8
#define FULLMASK 0xffffffffu
#define RS (HS+4)

__global__ void __launch_bounds__(256) dpp_score_kernel() {
    const int lane = threadIdx.x & 31;
    const int w    = threadIdx.x >> 5;
    const int i    = blockIdx.x * NW + w;
    const int head = blockIdx.y;

    const float* qh = g_q + (size_t)head*Tt*HS;
    const float* kh = g_k + (size_t)head*Tt*HS;
    const float* vh = g_v + (size_t)head*Tt*HS;
    const float* srow = g_s + ((size_t)head*Tt + i)*Tt;

    __shared__ __align__(16) float skr[NW][10][RS];
    __shared__ __align__(16) float svr[NW][9][RS];
    __shared__ float sG[NW][9][9];
    __shared__ float sdv[NW][9];
    __shared__ int   sRows[NW][9];
    __shared__ float sCoeff[NW][9];

    float sv[16];
#pragma unroll
    for (int c4 = 0; c4 < 4; c4++) {
        float4 t = ((const float4*)srow)[lane + (c4 << 5)];
        int jb = (lane << 2) + (c4 << 7);
        sv[c4*4+0] = (jb+0 <= i) ? t.x : -INFINITY;
        sv[c4*4+1] = (jb+1 <= i) ? t.y : -INFINITY;
        sv[c4*4+2] = (jb+2 <= i) ? t.z : -INFINITY;
        sv[c4*4+3] = (jb+3 <= i) ? t.w : -INFINITY;
    }

    const int ncand = (i + 1 < 8) ? (i + 1) : 8;

    int top[8];
#pragma unroll
    for (int r = 0; r < 8; r++) {
        float bv = -INFINITY; int bi = 0x7fffffff;
#pragma unroll
        for (int idx = 0; idx < 16; idx++) {
            int j = (lane << 2) + ((idx >> 2) << 7) + (idx & 3);
            float v = sv[idx];
            if (v > bv || (v == bv && j < bi)) { bv = v; bi = j; }
        }
#pragma unroll
        for (int off = 16; off > 0; off >>= 1) {
            float ov = __shfl_xor_sync(FULLMASK, bv, off);
            int   oi = __shfl_xor_sync(FULLMASK, bi, off);
            if (ov > bv || (ov == bv && oi < bi)) { bv = ov; bi = oi; }
        }
        int sel = bi;
        if (sel < 0 || sel > i) sel = 0;
        top[r] = sel;
        if (((sel >> 2) & 31) == lane)
            sv[((sel >> 7) << 2) | (sel & 3)] = -INFINITY;
    }

    if (lane == 0) {
        sRows[w][0] = i;
#pragma unroll
        for (int r = 0; r < 8; r++) sRows[w][r+1] = top[r];
    }
    __syncwarp();

    for (int e = lane; e < 9*16; e += 32) {
        int r = e >> 4, f = e & 15;
        int row = sRows[w][r];
        *(float4*)&skr[w][r][f<<2] = ((const float4*)(kh + (size_t)row*HS))[f];
        *(float4*)&svr[w][r][f<<2] = ((const float4*)(vh + (size_t)row*HS))[f];
    }
    if (lane < 16)
        *(float4*)&skr[w][9][lane<<2] = ((const float4*)(qh + (size_t)i*HS))[lane];
    __syncwarp();

    {
        int t0 = lane, t1 = lane + 32;
        int r0 = cTR[t0], c0 = cTC[t0];
        int r1 = (t1 < 54) ? cTR[t1] : 0;
        int c1 = (t1 < 54) ? cTC[t1] : 0;
        float a0 = 0.f, a1 = 0.f;
#pragma unroll
        for (int f = 0; f < 16; f++) {
            float4 x0 = *(const float4*)&skr[w][r0][f<<2];
            float4 y0 = *(const float4*)&skr[w][c0][f<<2];
            a0 += x0.x*y0.x + x0.y*y0.y + x0.z*y0.z + x0.w*y0.w;
            float4 x1 = *(const float4*)&skr[w][r1][f<<2];
            float4 y1 = *(const float4*)&skr[w][c1][f<<2];
            a1 += x1.x*y1.x + x1.y*y1.y + x1.z*y1.z + x1.w*y1.w;
        }
        if (c0 == 9) sdv[w][r0] = a0 * 0.125f;
        else { sG[w][r0][c0] = a0; sG[w][c0][r0] = a0; }
        if (t1 < 54) {
            if (c1 == 9) sdv[w][r1] = a1 * 0.125f;
            else { sG[w][r1][c1] = a1; sG[w][c1][r1] = a1; }
        }
    }
    __syncwarp();

    float sc0 = -INFINITY, sc1 = -INFINITY;
    float w00=0,w01=0,w02=0, w10=0,w11=0,w12=0;
    int a0i=-1, b0i=-1, a1i=-1, b1i=-1;
#pragma unroll
    for (int half = 0; half < 2; half++) {
        int cid = lane + (half << 5);
        if (cid >= 36) break;
        int a, b, sz;
        if (cid < 8) { sz = 2; a = cid; b = -1; }
        else         { sz = 3; a = cPA[cid-8]; b = cPB[cid-8]; }
        bool valid = (a < ncand) && (sRows[w][a+1] != i);
        if (b >= 0) valid = valid && (b < ncand) && (sRows[w][b+1] != i);
        float score = -INFINITY, x0 = 0.f, x1 = 0.f, x2 = 0.f;
        if (valid) {
            int ra = a + 1;
            if (sz == 2) {
                float det = sG[w][0][0]*sG[w][ra][ra] - sG[w][0][ra]*sG[w][0][ra];
                score = logf(det + 1e-6f) * 0.5f;
                float d0 = sdv[w][0], d1 = sdv[w][ra];
                float m = fmaxf(d0, d1);
                float e0 = expf(d0-m), e1 = expf(d1-m);
                float inv = 1.f/(e0+e1);
                x0 = e0*inv; x1 = e1*inv;
            } else {
                int rb = b + 1;
                float g00=sG[w][0][0],  g01=sG[w][0][ra],  g02=sG[w][0][rb];
                float g11=sG[w][ra][ra], g12=sG[w][ra][rb], g22=sG[w][rb][rb];
                float det = g00*(g11*g22 - g12*g12)
                          - g01*(g01*g22 - g12*g02)
                          + g02*(g01*g12 - g11*g02);
                score = logf(det + 1e-6f) * (1.f/3.f);
                float d0=sdv[w][0], d1=sdv[w][ra], d2=sdv[w][rb];
                float m = fmaxf(d0, fmaxf(d1, d2));
                float e0=expf(d0-m), e1=expf(d1-m), e2=expf(d2-m);
                float inv = 1.f/(e0+e1+e2);
                x0=e0*inv; x1=e1*inv; x2=e2*inv;
            }
        }
        if (half == 0) { sc0=score; w00=x0; w01=x1; w02=x2; a0i=a; b0i=b; }
        else           { sc1=score; w10=x0; w11=x1; w12=x2; a1i=a; b1i=b; }
    }

    float mx = fmaxf(sc0, sc1);
#pragma unroll
    for (int off = 16; off > 0; off >>= 1)
        mx = fmaxf(mx, __shfl_xor_sync(FULLMASK, mx, off));

    if (lane < 9) sCoeff[w][lane] = 0.f;
    __syncwarp();

    if (mx == -INFINITY) {
        if (lane == 0) sCoeff[w][0] = 1.f;
        __syncwarp();
    } else {
        float p0 = (sc0 == -INFINITY) ? 0.f : expf(sc0 - mx);
        float p1 = (sc1 == -INFINITY) ? 0.f : expf(sc1 - mx);
        float s = p0 + p1;
#pragma unroll
        for (int off = 16; off > 0; off >>= 1)
            s += __shfl_xor_sync(FULLMASK, s, off);
        float invs = 1.f / s;
        if (p0 > 0.f) {
            float p = p0 * invs;
            atomicAdd(&sCoeff[w][0],     p * w00);
            atomicAdd(&sCoeff[w][a0i+1], p * w01);
            if (b0i >= 0) atomicAdd(&sCoeff[w][b0i+1], p * w02);
        }
        if (p1 > 0.f) {
            float p = p1 * invs;
            atomicAdd(&sCoeff[w][0],     p * w10);
            atomicAdd(&sCoeff[w][a1i+1], p * w11);
            if (b1i >= 0) atomicAdd(&sCoeff[w][b1i+1], p * w12);
        }
        __syncwarp();
    }

    int bb = head / Hh, h = head - bb*Hh;
    float* ybase = g_y + ((size_t)(bb*Tt + i))*Cc + h*HS;
#pragma unroll
    for (int half = 0; half < 2; half++) {
        int d = lane + (half << 5);
        float y = 0.f;
#pragma unroll
        for (int r = 0; r < 9; r++) y += sCoeff[w][r] * svr[w][r][d];
        ybase[d] = y;
    }
}

// ---------------------------------------------------------------------------
extern "C" void kernel_launch(void* const* d_in, const int* in_sizes, int n_in,
                              void* d_out, int out_size) {
    const float* x      = (const float*)d_in[0];
    const float* W_attn = (const float*)d_in[1];
    const float* b_attn = (const float*)d_in[2];
    const float* W_proj = (const float*)d_in[3];
    const float* b_proj = (const float*)d_in[4];
    float* out = (float*)d_out;

    dim3 g1(3*Cc/QBN, Bb*Tt/QBM);     // 18 x 8 = 144 blocks
    gemm_qkv_kernel<<<g1, 256>>>(x, W_attn, b_attn);

    dim3 gs(Tt/64, Tt/64, BHn);       // 8 x 8 x 24 (upper blocks early-exit)
    sims_kernel<<<gs, 256>>>();

    dim3 g2(Tt/NW, BHn);              // 64 x 24
    dpp_score_kernel<<<g2, 256>>>();

    dim3 g3(Cc/PBN, Bb*Tt/PBM);       // 12 x 16 = 192 blocks
    gemm_proj_kernel<<<g3, 128>>>(W_proj, b_proj, out);
}

// round 14
// speedup vs baseline: 5.3953x; 1.0349x over previous
#include <cuda_runtime.h>
#include <math.h>
#include <stdint.h>

#define Bb 2
#define Tt 512
#define Cc 768
#define Hh 12
#define HS 64
#define BHn (Bb*Hh)

typedef unsigned long long ull;

// scratch (allocation-free rule: __device__ globals)
__device__ float g_q[BHn*Tt*HS];
__device__ float g_k[BHn*Tt*HS];
__device__ float g_v[BHn*Tt*HS];
__device__ float g_y[Bb*Tt*Cc];
__device__ float g_s[(size_t)BHn*Tt*Tt];   // causal sim matrix per head

// lexicographic pairs (a<b) over 8 slots, matching itertools.combinations order
__constant__ int cPA[28] = {0,0,0,0,0,0,0,1,1,1,1,1,1,2,2,2,2,2,3,3,3,3,4,4,4,5,5,6};
__constant__ int cPB[28] = {1,2,3,4,5,6,7,2,3,4,5,6,7,3,4,5,6,7,4,5,6,7,5,6,7,6,7,7};

// 54 dot-tasks: 45 gram pairs (r<=c) + 9 q-dots (c==9 means q)
__constant__ int cTR[54] = {0,0,0,0,0,0,0,0,0, 1,1,1,1,1,1,1,1, 2,2,2,2,2,2,2,
                            3,3,3,3,3,3, 4,4,4,4,4, 5,5,5,5, 6,6,6, 7,7, 8,
                            0,1,2,3,4,5,6,7,8};
__constant__ int cTC[54] = {0,1,2,3,4,5,6,7,8, 1,2,3,4,5,6,7,8, 2,3,4,5,6,7,8,
                            3,4,5,6,7,8, 4,5,6,7,8, 5,6,7,8, 6,7,8, 7,8, 8,
                            9,9,9,9,9,9,9,9,9};

// ---------------------------------------------------------------------------
// packed dual-fp32 FMA helpers (used in sims kernel only)
// ---------------------------------------------------------------------------
__device__ __forceinline__ ull pk2(float x) {
    ull r; uint32_t b = __float_as_uint(x);
    asm("mov.b64 %0, {%1, %1};" : "=l"(r) : "r"(b));
    return r;
}
__device__ __forceinline__ void ffma2(ull& acc, ull a, ull b) {
    asm("fma.rn.f32x2 %0, %1, %2, %0;" : "+l"(acc) : "l"(a), "l"(b));
}
__device__ __forceinline__ float lo32(ull v) { return __uint_as_float((uint32_t)v); }
__device__ __forceinline__ float hi32(ull v) { return __uint_as_float((uint32_t)(v >> 32)); }

// ---------------------------------------------------------------------------
// fused QKV GEMM (fp32): C = x·W_attnᵀ + b, scatter to g_q/g_k/g_v
// 128x64 tile, 256 threads, 8x4 micro-tile (rows split 4+4), BK=16,
// smem double-buffer + register-staged prefetch. 288 blocks (~2/SM).
// ---------------------------------------------------------------------------
#define QBM 128
#define QBN 64
#define QBK 16
#define QNC (Cc/QBK)   // 48

__global__ void __launch_bounds__(256) gemm_qkv_kernel(
    const float* __restrict__ A,     // x [1024,768]
    const float* __restrict__ Bm,    // W_attn [2304,768]
    const float* __restrict__ bias)  // b_attn [2304]
{
    const int K = Cc;
    __shared__ __align__(16) float As[2][QBK][QBM+4];
    __shared__ __align__(16) float Bs[2][QBK][QBN+4];
    const int tid = threadIdx.x;
    const int tx = tid & 15, ty = tid >> 4;      // tx: n group, ty: 0..15 m group
    const int m0 = blockIdx.y * QBM, n0 = blockIdx.x * QBN;

    const int lr = tid >> 2;            // 0..63
    const int lc = (tid & 3) << 2;      // 0,4,8,12
    const float* Ap = A  + (size_t)(m0 + lr)*K + lc;   // rows lr, lr+64
    const float* Bp = Bm + (size_t)(n0 + lr)*K + lc;   // rows lr (0..63)

    float4 ra0, ra1, rb0;
    ra0 = *(const float4*)(Ap);
    ra1 = *(const float4*)(Ap + (size_t)64*K);
    rb0 = *(const float4*)(Bp);
    {
        As[0][lc+0][lr]=ra0.x; As[0][lc+1][lr]=ra0.y; As[0][lc+2][lr]=ra0.z; As[0][lc+3][lr]=ra0.w;
        As[0][lc+0][64+lr]=ra1.x; As[0][lc+1][64+lr]=ra1.y; As[0][lc+2][64+lr]=ra1.z; As[0][lc+3][64+lr]=ra1.w;
        Bs[0][lc+0][lr]=rb0.x; Bs[0][lc+1][lr]=rb0.y; Bs[0][lc+2][lr]=rb0.z; Bs[0][lc+3][lr]=rb0.w;
    }
    __syncthreads();

    float acc[8][4];
#pragma unroll
    for (int i=0;i<8;i++)
#pragma unroll
      for (int j=0;j<4;j++) acc[i][j]=0.f;

    int cur = 0;
    for (int kc = 0; kc < QNC; kc++) {
        if (kc + 1 < QNC) {
            int k0 = (kc + 1) * QBK;
            ra0 = *(const float4*)(Ap + k0);
            ra1 = *(const float4*)(Ap + (size_t)64*K + k0);
            rb0 = *(const float4*)(Bp + k0);
        }
#pragma unroll
        for (int kk = 0; kk < QBK; kk++) {
            float4 a0 = *(const float4*)&As[cur][kk][ty<<2];
            float4 a1 = *(const float4*)&As[cur][kk][64+(ty<<2)];
            float4 b  = *(const float4*)&Bs[cur][kk][tx<<2];
            float av[8] = {a0.x,a0.y,a0.z,a0.w, a1.x,a1.y,a1.z,a1.w};
#pragma unroll
            for (int i = 0; i < 8; i++) {
                acc[i][0] += av[i]*b.x;
                acc[i][1] += av[i]*b.y;
                acc[i][2] += av[i]*b.z;
                acc[i][3] += av[i]*b.w;
            }
        }
        if (kc + 1 < QNC) {
            int nb = cur ^ 1;
            As[nb][lc+0][lr]=ra0.x; As[nb][lc+1][lr]=ra0.y; As[nb][lc+2][lr]=ra0.z; As[nb][lc+3][lr]=ra0.w;
            As[nb][lc+0][64+lr]=ra1.x; As[nb][lc+1][64+lr]=ra1.y; As[nb][lc+2][64+lr]=ra1.z; As[nb][lc+3][64+lr]=ra1.w;
            Bs[nb][lc+0][lr]=rb0.x; Bs[nb][lc+1][lr]=rb0.y; Bs[nb][lc+2][lr]=rb0.z; Bs[nb][lc+3][lr]=rb0.w;
        }
        __syncthreads();
        cur ^= 1;
    }

    // epilogue: scatter 8x4 outputs
#pragma unroll
    for (int im = 0; im < 8; im++) {
        int m = m0 + ((im < 4) ? ((ty<<2) + im) : (64 + (ty<<2) + im - 4));
        int b = m >> 9, t = m & 511;
#pragma unroll
        for (int jn = 0; jn < 4; jn++) {
            int n = n0 + (tx<<2) + jn;
            float val = acc[im][jn] + bias[n];
            int part = n / Cc;
            int c = n - part*Cc;
            int h = c >> 6;
            int d = c & 63;
            float* dst = (part==0) ? g_q : (part==1) ? g_k : g_v;
            dst[(((size_t)(b*Hh + h))*Tt + t)*HS + d] = val;
        }
    }
}

// ---------------------------------------------------------------------------
// zero kernel for out (proj accumulates via atomicAdd)
// ---------------------------------------------------------------------------
__global__ void __launch_bounds__(256) zero_out_kernel(float* __restrict__ out) {
    int idx = blockIdx.x * 256 + threadIdx.x;
    ((float4*)out)[idx] = make_float4(0.f, 0.f, 0.f, 0.f);
}

// ---------------------------------------------------------------------------
// proj GEMM (fp32, split-K=2): out += g_y·W_projᵀ (+ b on split 0)
// 64x64 tile, 128 threads, 8x4 micro-tile, BK=16, dbl-buffer. 384 blocks.
// ---------------------------------------------------------------------------
#define PBM 64
#define PBN 64
#define PBK 16
#define PKS (Cc/2)       // 384 per split
#define PNC (PKS/PBK)    // 24 chunks

__global__ void __launch_bounds__(128) gemm_proj_kernel(
    const float* __restrict__ Bm,    // W_proj [768,768]
    const float* __restrict__ bias,  // b_proj [768]
    float* __restrict__ out)         // [1024,768] pre-zeroed
{
    const int K = Cc;
    const float* A = g_y;
    __shared__ __align__(16) float As[2][PBK][PBM+4];
    __shared__ __align__(16) float Bs[2][PBK][PBN+4];
    const int tid = threadIdx.x;
    const int tx = tid & 15, ty = tid >> 4;     // ty 0..7
    const int m0 = blockIdx.y * PBM, n0 = blockIdx.x * PBN;
    const int kbase = blockIdx.z * PKS;

    const int lr = tid >> 2;            // 0..31 (+32 second half)
    const int lc = (tid & 3) << 2;
    const float* Ap = A  + (size_t)(m0 + lr)*K + kbase + lc;
    const float* Bp = Bm + (size_t)(n0 + lr)*K + kbase + lc;

    float4 ra0, ra1, rb0, rb1;
    ra0 = *(const float4*)(Ap);
    ra1 = *(const float4*)(Ap + (size_t)32*K);
    rb0 = *(const float4*)(Bp);
    rb1 = *(const float4*)(Bp + (size_t)32*K);
    {
        As[0][lc+0][lr]=ra0.x; As[0][lc+1][lr]=ra0.y; As[0][lc+2][lr]=ra0.z; As[0][lc+3][lr]=ra0.w;
        As[0][lc+0][32+lr]=ra1.x; As[0][lc+1][32+lr]=ra1.y; As[0][lc+2][32+lr]=ra1.z; As[0][lc+3][32+lr]=ra1.w;
        Bs[0][lc+0][lr]=rb0.x; Bs[0][lc+1][lr]=rb0.y; Bs[0][lc+2][lr]=rb0.z; Bs[0][lc+3][lr]=rb0.w;
        Bs[0][lc+0][32+lr]=rb1.x; Bs[0][lc+1][32+lr]=rb1.y; Bs[0][lc+2][32+lr]=rb1.z; Bs[0][lc+3][32+lr]=rb1.w;
    }
    __syncthreads();

    float acc[8][4];
#pragma unroll
    for (int i=0;i<8;i++)
#pragma unroll
      for (int j=0;j<4;j++) acc[i][j]=0.f;

    int cur = 0;
    for (int kc = 0; kc < PNC; kc++) {
        if (kc + 1 < PNC) {
            int k0 = (kc + 1) * PBK;
            ra0 = *(const float4*)(Ap + k0);
            ra1 = *(const float4*)(Ap + (size_t)32*K + k0);
            rb0 = *(const float4*)(Bp + k0);
            rb1 = *(const float4*)(Bp + (size_t)32*K + k0);
        }
#pragma unroll
        for (int kk = 0; kk < PBK; kk++) {
            float4 a0 = *(const float4*)&As[cur][kk][ty<<2];
            float4 a1 = *(const float4*)&As[cur][kk][32+(ty<<2)];
            float4 b  = *(const float4*)&Bs[cur][kk][tx<<2];
            float av[8] = {a0.x,a0.y,a0.z,a0.w, a1.x,a1.y,a1.z,a1.w};
#pragma unroll
            for (int i = 0; i < 8; i++) {
                acc[i][0] += av[i]*b.x;
                acc[i][1] += av[i]*b.y;
                acc[i][2] += av[i]*b.z;
                acc[i][3] += av[i]*b.w;
            }
        }
        if (kc + 1 < PNC) {
            int nb = cur ^ 1;
            As[nb][lc+0][lr]=ra0.x; As[nb][lc+1][lr]=ra0.y; As[nb][lc+2][lr]=ra0.z; As[nb][lc+3][lr]=ra0.w;
            As[nb][lc+0][32+lr]=ra1.x; As[nb][lc+1][32+lr]=ra1.y; As[nb][lc+2][32+lr]=ra1.z; As[nb][lc+3][32+lr]=ra1.w;
            Bs[nb][lc+0][lr]=rb0.x; Bs[nb][lc+1][lr]=rb0.y; Bs[nb][lc+2][lr]=rb0.z; Bs[nb][lc+3][lr]=rb0.w;
            Bs[nb][lc+0][32+lr]=rb1.x; Bs[nb][lc+1][32+lr]=rb1.y; Bs[nb][lc+2][32+lr]=rb1.z; Bs[nb][lc+3][32+lr]=rb1.w;
        }
        __syncthreads();
        cur ^= 1;
    }

    const bool addb = (blockIdx.z == 0);
#pragma unroll
    for (int im = 0; im < 8; im++) {
        int m = m0 + ((im < 4) ? ((ty<<2) + im) : (32 + (ty<<2) + im - 4));
        int n = n0 + (tx<<2);
        float* dst = out + (size_t)m*Cc + n;
#pragma unroll
        for (int j = 0; j < 4; j++) {
            float val = acc[im][j] + (addb ? bias[n+j] : 0.f);
            atomicAdd(dst + j, val);
        }
    }
}

// ---------------------------------------------------------------------------
// sims kernel (fp32, FFMA2): S[h][i][j] = q_i·k_j, lower-triangular blocks
// ---------------------------------------------------------------------------
#define SBK 16
#define SBM 64
#define SBN 64

__global__ void __launch_bounds__(256) sims_kernel() {
    if (blockIdx.x > blockIdx.y) return;
    const int head = blockIdx.z;
    const int m0 = blockIdx.y * 64;
    const int n0 = blockIdx.x * 64;
    const float* Qh = g_q + (size_t)head*Tt*HS;
    const float* Kh = g_k + (size_t)head*Tt*HS;
    float* Sh = g_s + (size_t)head*Tt*Tt;

    __shared__ __align__(16) float As[SBK][SBM+4];
    __shared__ __align__(16) float Bs[SBK][SBN+4];
    int tid = threadIdx.x;
    int tx = tid & 15, ty = tid >> 4;
    int lr = tid >> 2;
    int lk = (tid & 3) << 2;
    ull acc2[4][2] = {};
    for (int k0 = 0; k0 < HS; k0 += SBK) {
        float4 av = *(const float4*)(Qh + (size_t)(m0+lr)*HS + k0 + lk);
        float4 bv = *(const float4*)(Kh + (size_t)(n0+lr)*HS + k0 + lk);
        As[lk+0][lr]=av.x; As[lk+1][lr]=av.y; As[lk+2][lr]=av.z; As[lk+3][lr]=av.w;
        Bs[lk+0][lr]=bv.x; Bs[lk+1][lr]=bv.y; Bs[lk+2][lr]=bv.z; Bs[lk+3][lr]=bv.w;
        __syncthreads();
#pragma unroll
        for (int kk = 0; kk < SBK; kk++) {
            float4 a = *(const float4*)&As[kk][ty<<2];
            const ull* bp = (const ull*)&Bs[kk][tx<<2];
            ull b0 = bp[0], b1 = bp[1];
            ull a0 = pk2(a.x), a1 = pk2(a.y), a2 = pk2(a.z), a3 = pk2(a.w);
            ffma2(acc2[0][0], a0, b0); ffma2(acc2[0][1], a0, b1);
            ffma2(acc2[1][0], a1, b0); ffma2(acc2[1][1], a1, b1);
            ffma2(acc2[2][0], a2, b0); ffma2(acc2[2][1], a2, b1);
            ffma2(acc2[3][0], a3, b0); ffma2(acc2[3][1], a3, b1);
        }
        __syncthreads();
    }
#pragma unroll
    for (int im = 0; im < 4; im++) {
#pragma unroll
        for (int jp = 0; jp < 2; jp++) {
            int m = m0 + (ty<<2) + im;
            int n = n0 + (tx<<2) + (jp<<1);
            Sh[(size_t)m*Tt + n  ] = lo32(acc2[im][jp]);
            Sh[(size_t)m*Tt + n+1] = hi32(acc2[im][jp]);
        }
    }
}

// ---------------------------------------------------------------------------
// DPP score kernel: WARP per (token, head). float4 loads throughout.
// ---------------------------------------------------------------------------
#define NW 8
#define FULLMASK 0xffffffffu
#define RS (HS+4)

__global__ void __launch_bounds__(256) dpp_score_kernel() {
    const int lane = threadIdx.x & 31;
    const int w    = threadIdx.x >> 5;
    const int i    = blockIdx.x * NW + w;
    const int head = blockIdx.y;

    const float* qh = g_q + (size_t)head*Tt*HS;
    const float* kh = g_k + (size_t)head*Tt*HS;
    const float* vh = g_v + (size_t)head*Tt*HS;
    const float* srow = g_s + ((size_t)head*Tt + i)*Tt;

    __shared__ __align__(16) float skr[NW][10][RS];
    __shared__ __align__(16) float svr[NW][9][RS];
    __shared__ float sG[NW][9][9];
    __shared__ float sdv[NW][9];
    __shared__ int   sRows[NW][9];
    __shared__ float sCoeff[NW][9];

    float sv[16];
#pragma unroll
    for (int c4 = 0; c4 < 4; c4++) {
        float4 t = ((const float4*)srow)[lane + (c4 << 5)];
        int jb = (lane << 2) + (c4 << 7);
        sv[c4*4+0] = (jb+0 <= i) ? t.x : -INFINITY;
        sv[c4*4+1] = (jb+1 <= i) ? t.y : -INFINITY;
        sv[c4*4+2] = (jb+2 <= i) ? t.z : -INFINITY;
        sv[c4*4+3] = (jb+3 <= i) ? t.w : -INFINITY;
    }

    const int ncand = (i + 1 < 8) ? (i + 1) : 8;

    int top[8];
#pragma unroll
    for (int r = 0; r < 8; r++) {
        float bv = -INFINITY; int bi = 0x7fffffff;
#pragma unroll
        for (int idx = 0; idx < 16; idx++) {
            int j = (lane << 2) + ((idx >> 2) << 7) + (idx & 3);
            float v = sv[idx];
            if (v > bv || (v == bv && j < bi)) { bv = v; bi = j; }
        }
#pragma unroll
        for (int off = 16; off > 0; off >>= 1) {
            float ov = __shfl_xor_sync(FULLMASK, bv, off);
            int   oi = __shfl_xor_sync(FULLMASK, bi, off);
            if (ov > bv || (ov == bv && oi < bi)) { bv = ov; bi = oi; }
        }
        int sel = bi;
        if (sel < 0 || sel > i) sel = 0;
        top[r] = sel;
        if (((sel >> 2) & 31) == lane)
            sv[((sel >> 7) << 2) | (sel & 3)] = -INFINITY;
    }

    if (lane == 0) {
        sRows[w][0] = i;
#pragma unroll
        for (int r = 0; r < 8; r++) sRows[w][r+1] = top[r];
    }
    __syncwarp();

    for (int e = lane; e < 9*16; e += 32) {
        int r = e >> 4, f = e & 15;
        int row = sRows[w][r];
        *(float4*)&skr[w][r][f<<2] = ((const float4*)(kh + (size_t)row*HS))[f];
        *(float4*)&svr[w][r][f<<2] = ((const float4*)(vh + (size_t)row*HS))[f];
    }
    if (lane < 16)
        *(float4*)&skr[w][9][lane<<2] = ((const float4*)(qh + (size_t)i*HS))[lane];
    __syncwarp();

    {
        int t0 = lane, t1 = lane + 32;
        int r0 = cTR[t0], c0 = cTC[t0];
        int r1 = (t1 < 54) ? cTR[t1] : 0;
        int c1 = (t1 < 54) ? cTC[t1] : 0;
        float a0 = 0.f, a1 = 0.f;
#pragma unroll
        for (int f = 0; f < 16; f++) {
            float4 x0 = *(const float4*)&skr[w][r0][f<<2];
            float4 y0 = *(const float4*)&skr[w][c0][f<<2];
            a0 += x0.x*y0.x + x0.y*y0.y + x0.z*y0.z + x0.w*y0.w;
            float4 x1 = *(const float4*)&skr[w][r1][f<<2];
            float4 y1 = *(const float4*)&skr[w][c1][f<<2];
            a1 += x1.x*y1.x + x1.y*y1.y + x1.z*y1.z + x1.w*y1.w;
        }
        if (c0 == 9) sdv[w][r0] = a0 * 0.125f;
        else { sG[w][r0][c0] = a0; sG[w][c0][r0] = a0; }
        if (t1 < 54) {
            if (c1 == 9) sdv[w][r1] = a1 * 0.125f;
            else { sG[w][r1][c1] = a1; sG[w][c1][r1] = a1; }
        }
    }
    __syncwarp();

    float sc0 = -INFINITY, sc1 = -INFINITY;
    float w00=0,w01=0,w02=0, w10=0,w11=0,w12=0;
    int a0i=-1, b0i=-1, a1i=-1, b1i=-1;
#pragma unroll
    for (int half = 0; half < 2; half++) {
        int cid = lane + (half << 5);
        if (cid >= 36) break;
        int a, b, sz;
        if (cid < 8) { sz = 2; a = cid; b = -1; }
        else         { sz = 3; a = cPA[cid-8]; b = cPB[cid-8]; }
        bool valid = (a < ncand) && (sRows[w][a+1] != i);
        if (b >= 0) valid = valid && (b < ncand) && (sRows[w][b+1] != i);
        float score = -INFINITY, x0 = 0.f, x1 = 0.f, x2 = 0.f;
        if (valid) {
            int ra = a + 1;
            if (sz == 2) {
                float det = sG[w][0][0]*sG[w][ra][ra] - sG[w][0][ra]*sG[w][0][ra];
                score = logf(det + 1e-6f) * 0.5f;
                float d0 = sdv[w][0], d1 = sdv[w][ra];
                float m = fmaxf(d0, d1);
                float e0 = expf(d0-m), e1 = expf(d1-m);
                float inv = 1.f/(e0+e1);
                x0 = e0*inv; x1 = e1*inv;
            } else {
                int rb = b + 1;
                float g00=sG[w][0][0],  g01=sG[w][0][ra],  g02=sG[w][0][rb];
                float g11=sG[w][ra][ra], g12=sG[w][ra][rb], g22=sG[w][rb][rb];
                float det = g00*(g11*g22 - g12*g12)
                          - g01*(g01*g22 - g12*g02)
                          + g02*(g01*g12 - g11*g02);
                score = logf(det + 1e-6f) * (1.f/3.f);
                float d0=sdv[w][0], d1=sdv[w][ra], d2=sdv[w][rb];
                float m = fmaxf(d0, fmaxf(d1, d2));
                float e0=expf(d0-m), e1=expf(d1-m), e2=expf(d2-m);
                float inv = 1.f/(e0+e1+e2);
                x0=e0*inv; x1=e1*inv; x2=e2*inv;
            }
        }
        if (half == 0) { sc0=score; w00=x0; w01=x1; w02=x2; a0i=a; b0i=b; }
        else           { sc1=score; w10=x0; w11=x1; w12=x2; a1i=a; b1i=b; }
    }

    float mx = fmaxf(sc0, sc1);
#pragma unroll
    for (int off = 16; off > 0; off >>= 1)
        mx = fmaxf(mx, __shfl_xor_sync(FULLMASK, mx, off));

    if (lane < 9) sCoeff[w][lane] = 0.f;
    __syncwarp();

    if (mx == -INFINITY) {
        if (lane == 0) sCoeff[w][0] = 1.f;
        __syncwarp();
    } else {
        float p0 = (sc0 == -INFINITY) ? 0.f : expf(sc0 - mx);
        float p1 = (sc1 == -INFINITY) ? 0.f : expf(sc1 - mx);
        float s = p0 + p1;
#pragma unroll
        for (int off = 16; off > 0; off >>= 1)
            s += __shfl_xor_sync(FULLMASK, s, off);
        float invs = 1.f / s;
        if (p0 > 0.f) {
            float p = p0 * invs;
            atomicAdd(&sCoeff[w][0],     p * w00);
            atomicAdd(&sCoeff[w][a0i+1], p * w01);
            if (b0i >= 0) atomicAdd(&sCoeff[w][b0i+1], p * w02);
        }
        if (p1 > 0.f) {
            float p = p1 * invs;
            atomicAdd(&sCoeff[w][0],     p * w10);
            atomicAdd(&sCoeff[w][a1i+1], p * w11);
            if (b1i >= 0) atomicAdd(&sCoeff[w][b1i+1], p * w12);
        }
        __syncwarp();
    }

    int bb = head / Hh, h = head - bb*Hh;
    float* ybase = g_y + ((size_t)(bb*Tt + i))*Cc + h*HS;
#pragma unroll
    for (int half = 0; half < 2; half++) {
        int d = lane + (half << 5);
        float y = 0.f;
#pragma unroll
        for (int r = 0; r < 9; r++) y += sCoeff[w][r] * svr[w][r][d];
        ybase[d] = y;
    }
}

// ---------------------------------------------------------------------------
extern "C" void kernel_launch(void* const* d_in, const int* in_sizes, int n_in,
                              void* d_out, int out_size) {
    const float* x      = (const float*)d_in[0];
    const float* W_attn = (const float*)d_in[1];
    const float* b_attn = (const float*)d_in[2];
    const float* W_proj = (const float*)d_in[3];
    const float* b_proj = (const float*)d_in[4];
    float* out = (float*)d_out;

    dim3 g1(3*Cc/QBN, Bb*Tt/QBM);     // 36 x 8 = 288 blocks
    gemm_qkv_kernel<<<g1, 256>>>(x, W_attn, b_attn);

    dim3 gs(Tt/64, Tt/64, BHn);       // 8 x 8 x 24 (upper blocks early-exit)
    sims_kernel<<<gs, 256>>>();

    dim3 g2(Tt/NW, BHn);              // 64 x 24
    dpp_score_kernel<<<g2, 256>>>();

    zero_out_kernel<<<(Bb*Tt*Cc/4)/256, 256>>>(out);   // 768 blocks

    dim3 g3(Cc/PBN, Bb*Tt/PBM, 2);    // 12 x 16 x 2 = 384 blocks
    gemm_proj_kernel<<<g3, 128>>>(W_proj, b_proj, out);
}